// round 11
// baseline (speedup 1.0000x reference)
#include <cuda_runtime.h>
#include <math.h>

#define TOK   8192        // 8 * 1024 tokens
#define DIMC  768
#define QKVD  2304
#define MLPD  3072
#define SEQ   1024

// ---------------- scratch (device globals: no allocation allowed) ----------
__device__ float g_h1 [TOK * DIMC];
__device__ float g_qkv[TOK * QKVD];
__device__ float g_ao [TOK * DIMC];
__device__ float g_x2 [TOK * DIMC];
__device__ float g_h2 [TOK * DIMC];
__device__ float g_act[TOK * MLPD];

// ---------------- LayerNorm: one CTA per row, 256 threads -------------------
__global__ void __launch_bounds__(256) ln_kernel(const float* __restrict__ x,
                                                 const float* __restrict__ g,
                                                 const float* __restrict__ b,
                                                 float* __restrict__ out) {
    int row = blockIdx.x;
    int t = threadIdx.x;
    const float* xr = x + (size_t)row * DIMC;
    float v0 = xr[t], v1 = xr[t + 256], v2 = xr[t + 512];
    float s  = v0 + v1 + v2;
    float s2 = v0 * v0 + v1 * v1 + v2 * v2;
#pragma unroll
    for (int off = 16; off; off >>= 1) {
        s  += __shfl_xor_sync(0xffffffffu, s,  off);
        s2 += __shfl_xor_sync(0xffffffffu, s2, off);
    }
    __shared__ float rs[8], rs2[8];
    int w = t >> 5;
    if ((t & 31) == 0) { rs[w] = s; rs2[w] = s2; }
    __syncthreads();
    s = 0.f; s2 = 0.f;
#pragma unroll
    for (int i = 0; i < 8; i++) { s += rs[i]; s2 += rs2[i]; }
    float mu   = s  * (1.0f / DIMC);
    float var  = s2 * (1.0f / DIMC) - mu * mu;
    float rstd = rsqrtf(var + 1e-5f);
    float* orow = out + (size_t)row * DIMC;
    orow[t      ] = (v0 - mu) * rstd * g[t      ] + b[t      ];
    orow[t + 256] = (v1 - mu) * rstd * g[t + 256] + b[t + 256];
    orow[t + 512] = (v2 - mu) * rstd * g[t + 512] + b[t + 512];
}

// ---------------- SGEMM 128x128x8, 256 threads, 8x8 per thread --------------
// A: MxK row-major, B: KxN row-major, C: MxN row-major.
// EPI 0: C = AB
// EPI 1: C = AB + bias[n] + res[m][n]
// EPI 2: C = gelu_exact(AB + bias[n])
template <int EPI>
__global__ void __launch_bounds__(256) sgemm_kernel(
    const float* __restrict__ A, const float* __restrict__ B,
    float* __restrict__ C, int M, int N, int K,
    const float* __restrict__ bias, const float* __restrict__ res) {
    __shared__ float As[8][128];   // stored transposed: As[k][m]
    __shared__ float Bs[8][128];   // Bs[k][n]
    int t  = threadIdx.x;
    int tx = t & 15, ty = t >> 4;
    int bm = blockIdx.y << 7, bn = blockIdx.x << 7;

    int arow = t >> 1;             // 0..127
    int akq  = (t & 1) << 2;       // 0 or 4
    int brow = t >> 5;             // 0..7
    int bcol = (t & 31) << 2;      // 0..124

    const float* Ap = A + (size_t)(bm + arow) * K + akq;
    const float* Bp = B + (size_t)brow * N + bn + bcol;

    float acc[8][8];
#pragma unroll
    for (int i = 0; i < 8; i++)
#pragma unroll
        for (int j = 0; j < 8; j++) acc[i][j] = 0.f;

    for (int k0 = 0; k0 < K; k0 += 8) {
        float4 a4 = *(const float4*)(Ap + k0);
        float4 b4 = *(const float4*)(Bp + (size_t)k0 * N);
        As[akq + 0][arow] = a4.x;
        As[akq + 1][arow] = a4.y;
        As[akq + 2][arow] = a4.z;
        As[akq + 3][arow] = a4.w;
        *(float4*)&Bs[brow][bcol] = b4;
        __syncthreads();
#pragma unroll
        for (int k = 0; k < 8; k++) {
            float af[8], bf[8];
            *(float4*)(af)     = *(const float4*)&As[k][ty << 3];
            *(float4*)(af + 4) = *(const float4*)&As[k][(ty << 3) + 4];
            *(float4*)(bf)     = *(const float4*)&Bs[k][tx << 3];
            *(float4*)(bf + 4) = *(const float4*)&Bs[k][(tx << 3) + 4];
#pragma unroll
            for (int i = 0; i < 8; i++)
#pragma unroll
                for (int j = 0; j < 8; j++)
                    acc[i][j] = fmaf(af[i], bf[j], acc[i][j]);
        }
        __syncthreads();
    }

#pragma unroll
    for (int i = 0; i < 8; i++) {
        int r = bm + (ty << 3) + i;
#pragma unroll
        for (int j4 = 0; j4 < 2; j4++) {
            int c = bn + (tx << 3) + (j4 << 2);
            float4 v;
            v.x = acc[i][j4 * 4 + 0];
            v.y = acc[i][j4 * 4 + 1];
            v.z = acc[i][j4 * 4 + 2];
            v.w = acc[i][j4 * 4 + 3];
            if (EPI == 1) {
                float4 bs = *(const float4*)&bias[c];
                float4 rr = *(const float4*)&res[(size_t)r * N + c];
                v.x += bs.x + rr.x; v.y += bs.y + rr.y;
                v.z += bs.z + rr.z; v.w += bs.w + rr.w;
            }
            if (EPI == 2) {
                float4 bs = *(const float4*)&bias[c];
                v.x += bs.x; v.y += bs.y; v.z += bs.z; v.w += bs.w;
                const float rs2i = 0.70710678118654752f;
                v.x = 0.5f * v.x * (1.0f + erff(v.x * rs2i));
                v.y = 0.5f * v.y * (1.0f + erff(v.y * rs2i));
                v.z = 0.5f * v.z * (1.0f + erff(v.z * rs2i));
                v.w = 0.5f * v.w * (1.0f + erff(v.w * rs2i));
            }
            *(float4*)&C[(size_t)r * N + c] = v;
        }
    }
}

// ---------------- fused flash attention ------------------------------------
// CTA = (qblock 0..15, head 0..11, batch 0..7). 64 queries x Dh=64 per CTA,
// streams 16 key blocks of 64. P tile aliases K tile (stride 65 padded).
__global__ void __launch_bounds__(256) attn_kernel() {
    extern __shared__ float sm[];
    float* Qs  = sm;          // [64][64]  stride 64
    float* KPs = sm + 4096;   // [64][65]  stride 65 (K tile, then P tile)
    float* Vs  = sm + 8256;   // [64][64]  stride 64

    int t  = threadIdx.x;
    int tx = t & 15, ty = t >> 4;
    int r0 = ty << 2, c0 = tx << 2;
    int qb = blockIdx.x, h = blockIdx.y, b = blockIdx.z;
    int qbase = b * SEQ + qb * 64;
    const float scale = 0.125f;   // 1/sqrt(64)

    // load Q tile
    for (int i = t; i < 1024; i += 256) {
        int row = i >> 4, d4 = (i & 15) << 2;
        float4 q4 = *(const float4*)&g_qkv[(size_t)(qbase + row) * QKVD + h * 64 + d4];
        *(float4*)&Qs[row * 64 + d4] = q4;
    }

    float o[4][4];
    float m[4], l[4];
#pragma unroll
    for (int i = 0; i < 4; i++) {
        m[i] = -1e30f; l[i] = 0.f;
#pragma unroll
        for (int j = 0; j < 4; j++) o[i][j] = 0.f;
    }

    for (int kb = 0; kb < 16; kb++) {
        int kvb = b * SEQ + kb * 64;
        __syncthreads();   // protect K/V/P reuse (and Q load on iter 0)
        for (int i = t; i < 1024; i += 256) {
            int row = i >> 4, d4 = (i & 15) << 2;
            float4 k4 = *(const float4*)&g_qkv[(size_t)(kvb + row) * QKVD + 768 + h * 64 + d4];
            float* kp = &KPs[row * 65 + d4];
            kp[0] = k4.x; kp[1] = k4.y; kp[2] = k4.z; kp[3] = k4.w;
            float4 v4 = *(const float4*)&g_qkv[(size_t)(kvb + row) * QKVD + 1536 + h * 64 + d4];
            *(float4*)&Vs[row * 64 + d4] = v4;
        }
        __syncthreads();

        // S = Q K^T (4x4 per thread)
        float s[4][4];
#pragma unroll
        for (int i = 0; i < 4; i++)
#pragma unroll
            for (int j = 0; j < 4; j++) s[i][j] = 0.f;
        for (int d = 0; d < 64; d++) {
            float qf[4], kf[4];
#pragma unroll
            for (int i = 0; i < 4; i++) qf[i] = Qs[(r0 + i) * 64 + d];
#pragma unroll
            for (int j = 0; j < 4; j++) kf[j] = KPs[(c0 + j) * 65 + d];
#pragma unroll
            for (int i = 0; i < 4; i++)
#pragma unroll
                for (int j = 0; j < 4; j++)
                    s[i][j] = fmaf(qf[i], kf[j], s[i][j]);
        }

        // online softmax (row reduction across the 16 tx lanes)
#pragma unroll
        for (int i = 0; i < 4; i++) {
#pragma unroll
            for (int j = 0; j < 4; j++) s[i][j] *= scale;
            float mx = fmaxf(fmaxf(s[i][0], s[i][1]), fmaxf(s[i][2], s[i][3]));
#pragma unroll
            for (int off = 8; off; off >>= 1)
                mx = fmaxf(mx, __shfl_xor_sync(0xffffffffu, mx, off));
            float mn = fmaxf(m[i], mx);
            float f  = __expf(m[i] - mn);
            m[i] = mn;
            float sum = 0.f;
#pragma unroll
            for (int j = 0; j < 4; j++) {
                s[i][j] = __expf(s[i][j] - mn);
                sum += s[i][j];
            }
#pragma unroll
            for (int off = 8; off; off >>= 1)
                sum += __shfl_xor_sync(0xffffffffu, sum, off);
            l[i] = l[i] * f + sum;
#pragma unroll
            for (int j = 0; j < 4; j++) o[i][j] *= f;
        }

        __syncthreads();   // all threads done reading K tile
#pragma unroll
        for (int i = 0; i < 4; i++)
#pragma unroll
            for (int j = 0; j < 4; j++)
                KPs[(r0 + i) * 65 + c0 + j] = s[i][j];
        __syncthreads();

        // O += P V
        for (int j = 0; j < 64; j++) {
            float pf[4];
#pragma unroll
            for (int i = 0; i < 4; i++) pf[i] = KPs[(r0 + i) * 65 + j];
            float4 v4 = *(const float4*)&Vs[j * 64 + c0];
#pragma unroll
            for (int i = 0; i < 4; i++) {
                o[i][0] = fmaf(pf[i], v4.x, o[i][0]);
                o[i][1] = fmaf(pf[i], v4.y, o[i][1]);
                o[i][2] = fmaf(pf[i], v4.z, o[i][2]);
                o[i][3] = fmaf(pf[i], v4.w, o[i][3]);
            }
        }
    }

#pragma unroll
    for (int i = 0; i < 4; i++) {
        float inv = 1.0f / l[i];
        float4 v;
        v.x = o[i][0] * inv; v.y = o[i][1] * inv;
        v.z = o[i][2] * inv; v.w = o[i][3] * inv;
        *(float4*)&g_ao[(size_t)(qbase + r0 + i) * DIMC + h * 64 + c0] = v;
    }
}

// ---------------- launch -----------------------------------------------------
extern "C" void kernel_launch(void* const* d_in, const int* in_sizes, int n_in,
                              void* d_out, int out_size) {
    (void)in_sizes; (void)n_in; (void)out_size;
    const float* x     = (const float*)d_in[0];
    const float* ln1_g = (const float*)d_in[1];
    const float* ln1_b = (const float*)d_in[2];
    const float* w_qkv = (const float*)d_in[3];
    const float* w_out = (const float*)d_in[4];
    const float* b_out = (const float*)d_in[5];
    const float* ln2_g = (const float*)d_in[6];
    const float* ln2_b = (const float*)d_in[7];
    const float* w1    = (const float*)d_in[8];
    const float* b1    = (const float*)d_in[9];
    const float* w2    = (const float*)d_in[10];
    const float* b2    = (const float*)d_in[11];
    float* out = (float*)d_out;

    float *h1, *qkv, *ao, *x2, *h2, *act;
    cudaGetSymbolAddress((void**)&h1,  g_h1);
    cudaGetSymbolAddress((void**)&qkv, g_qkv);
    cudaGetSymbolAddress((void**)&ao,  g_ao);
    cudaGetSymbolAddress((void**)&x2,  g_x2);
    cudaGetSymbolAddress((void**)&h2,  g_h2);
    cudaGetSymbolAddress((void**)&act, g_act);

    cudaFuncSetAttribute(attn_kernel,
                         cudaFuncAttributeMaxDynamicSharedMemorySize, 49408);

    // 1) h1 = LN1(x)
    ln_kernel<<<TOK, 256>>>(x, ln1_g, ln1_b, h1);
    // 2) qkv = h1 @ w_qkv              (8192 x 2304 x 768)
    sgemm_kernel<0><<<dim3(QKVD / 128, TOK / 128), 256>>>(
        h1, w_qkv, qkv, TOK, QKVD, DIMC, nullptr, nullptr);
    // 3) fused attention -> g_ao
    attn_kernel<<<dim3(16, 12, 8), 256, 49408>>>();
    // 4) x2 = x + ao @ w_out + b_out   (8192 x 768 x 768)
    sgemm_kernel<1><<<dim3(DIMC / 128, TOK / 128), 256>>>(
        ao, w_out, x2, TOK, DIMC, DIMC, b_out, x);
    // 5) h2 = LN2(x2)
    ln_kernel<<<TOK, 256>>>(x2, ln2_g, ln2_b, h2);
    // 6) act = gelu(h2 @ w1 + b1)      (8192 x 3072 x 768)
    sgemm_kernel<2><<<dim3(MLPD / 128, TOK / 128), 256>>>(
        h2, w1, act, TOK, MLPD, DIMC, b1, nullptr);
    // 7) out = x2 + act @ w2 + b2      (8192 x 768 x 3072)
    sgemm_kernel<1><<<dim3(DIMC / 128, TOK / 128), 256>>>(
        act, w2, out, TOK, DIMC, MLPD, b2, x2);
}

// round 13
// speedup vs baseline: 1.9233x; 1.9233x over previous
#include <cuda_runtime.h>
#include <cuda_bf16.h>
#include <stdint.h>
#include <cstdint>
#include <math.h>

#define TOK   8192        // 8 * 1024 tokens
#define DIMC  768
#define QKVD  2304
#define MLPD  3072
#define SEQ   1024

#define PADA  40          // A smem row stride (bf16): 32 + 8  -> ldmatrix conflict-free
#define PADB  136         // B smem row stride (bf16): 128 + 8 -> ldmatrix conflict-free

// ---------------- scratch (device globals: no allocation allowed) ----------
__device__ float g_h1 [TOK * DIMC];
__device__ float g_qkv[TOK * QKVD];
__device__ float g_ao [TOK * DIMC];
__device__ float g_x2 [TOK * DIMC];
__device__ float g_h2 [TOK * DIMC];
__device__ float g_act[TOK * MLPD];

// ---------------- LayerNorm: one CTA per row, 256 threads -------------------
__global__ void __launch_bounds__(256) ln_kernel(const float* __restrict__ x,
                                                 const float* __restrict__ g,
                                                 const float* __restrict__ b,
                                                 float* __restrict__ out) {
    int row = blockIdx.x;
    int t = threadIdx.x;
    const float* xr = x + (size_t)row * DIMC;
    float v0 = xr[t], v1 = xr[t + 256], v2 = xr[t + 512];
    float s  = v0 + v1 + v2;
    float s2 = v0 * v0 + v1 * v1 + v2 * v2;
#pragma unroll
    for (int off = 16; off; off >>= 1) {
        s  += __shfl_xor_sync(0xffffffffu, s,  off);
        s2 += __shfl_xor_sync(0xffffffffu, s2, off);
    }
    __shared__ float rs[8], rs2[8];
    int w = t >> 5;
    if ((t & 31) == 0) { rs[w] = s; rs2[w] = s2; }
    __syncthreads();
    s = 0.f; s2 = 0.f;
#pragma unroll
    for (int i = 0; i < 8; i++) { s += rs[i]; s2 += rs2[i]; }
    float mu   = s  * (1.0f / DIMC);
    float var  = s2 * (1.0f / DIMC) - mu * mu;
    float rstd = rsqrtf(var + 1e-5f);
    float* orow = out + (size_t)row * DIMC;
    orow[t      ] = (v0 - mu) * rstd * g[t      ] + b[t      ];
    orow[t + 256] = (v1 - mu) * rstd * g[t + 256] + b[t + 256];
    orow[t + 512] = (v2 - mu) * rstd * g[t + 512] + b[t + 512];
}

// ---------------- tensor-core helpers ---------------------------------------
__device__ __forceinline__ void ldsm_x4(unsigned int* r, unsigned int addr) {
    asm volatile("ldmatrix.sync.aligned.m8n8.x4.shared.b16 {%0,%1,%2,%3}, [%4];"
                 : "=r"(r[0]), "=r"(r[1]), "=r"(r[2]), "=r"(r[3]) : "r"(addr));
}
__device__ __forceinline__ void ldsm_x2t(unsigned int* r, unsigned int addr) {
    asm volatile("ldmatrix.sync.aligned.m8n8.x2.trans.shared.b16 {%0,%1}, [%2];"
                 : "=r"(r[0]), "=r"(r[1]) : "r"(addr));
}
__device__ __forceinline__ void mma_bf16(float* d, const unsigned int* a,
                                         const unsigned int* b) {
    asm volatile(
        "mma.sync.aligned.m16n8k16.row.col.f32.bf16.bf16.f32 "
        "{%0,%1,%2,%3}, {%4,%5,%6,%7}, {%8,%9}, {%0,%1,%2,%3};"
        : "+f"(d[0]), "+f"(d[1]), "+f"(d[2]), "+f"(d[3])
        : "r"(a[0]), "r"(a[1]), "r"(a[2]), "r"(a[3]), "r"(b[0]), "r"(b[1]));
}
__device__ __forceinline__ unsigned int packbf(float a, float b) {
    __nv_bfloat162 t = __floats2bfloat162_rn(a, b);   // .x = a (low), .y = b
    unsigned int u;
    u = *(unsigned int*)&t;
    return u;
}
// fp32 -> (hi, lo) bf16 split, 4 elements at a time
__device__ __forceinline__ void split4(float4 v, uint2& hi, uint2& lo) {
    float hx = __bfloat162float(__float2bfloat16(v.x));
    float hy = __bfloat162float(__float2bfloat16(v.y));
    float hz = __bfloat162float(__float2bfloat16(v.z));
    float hw = __bfloat162float(__float2bfloat16(v.w));
    hi.x = packbf(hx, hy);
    hi.y = packbf(hz, hw);
    lo.x = packbf(v.x - hx, v.y - hy);
    lo.y = packbf(v.z - hz, v.w - hw);
}

// ---------------- split-bf16 tensor-core GEMM --------------------------------
// C(MxN) = A(MxK) @ B(KxN), both fp32 row-major, computed as
// A_hi*B_hi + A_hi*B_lo + A_lo*B_hi in fp32 accumulators (error ~2^-18).
// CTA tile 128x128, K-tile 32. 8 warps, each 64x32 via m16n8k16 HMMA.
// EPI 0: C = AB
// EPI 1: C = AB + bias[n] + res[m][n]
// EPI 2: C = gelu_exact(AB + bias[n])
template <int EPI>
__global__ void __launch_bounds__(256, 2) mma_gemm(
    const float* __restrict__ A, const float* __restrict__ B,
    float* __restrict__ C, int M, int N, int K,
    const float* __restrict__ bias, const float* __restrict__ res) {
    __shared__ __nv_bfloat16 Ah[128 * PADA];
    __shared__ __nv_bfloat16 Al[128 * PADA];
    __shared__ __nv_bfloat16 Bh[32 * PADB];
    __shared__ __nv_bfloat16 Bl[32 * PADB];

    int t = threadIdx.x;
    int lane = t & 31, wid = t >> 5;
    int wm = (wid >> 2) << 6;        // 0 or 64
    int wn = (wid & 3) << 5;         // 0,32,64,96
    int bm = blockIdx.y << 7, bn = blockIdx.x << 7;

    float acc[4][4][4];
#pragma unroll
    for (int mi = 0; mi < 4; mi++)
#pragma unroll
        for (int ni = 0; ni < 4; ni++)
#pragma unroll
            for (int k = 0; k < 4; k++) acc[mi][ni][k] = 0.f;

    // per-lane ldmatrix base addresses
    unsigned int aOff = (unsigned int)(((wm + (lane & 15)) * PADA + ((lane >> 4) << 3)) * 2);
    unsigned int bOff = (unsigned int)(((lane & 15) * PADB + wn) * 2);
    unsigned int aH = (unsigned int)__cvta_generic_to_shared(Ah) + aOff;
    unsigned int aL = (unsigned int)__cvta_generic_to_shared(Al) + aOff;
    unsigned int bH = (unsigned int)__cvta_generic_to_shared(Bh) + bOff;
    unsigned int bL = (unsigned int)__cvta_generic_to_shared(Bl) + bOff;

    const float* Ag = A + (size_t)bm * K;
    const float* Bg = B + bn;

    for (int k0 = 0; k0 < K; k0 += 32) {
        // load + split A tile 128x32
#pragma unroll
        for (int i = 0; i < 4; i++) {
            int idx = t + (i << 8);
            int row = idx >> 3, c4 = (idx & 7) << 2;
            float4 v = *(const float4*)(Ag + (size_t)row * K + k0 + c4);
            uint2 hi, lo;
            split4(v, hi, lo);
            *(uint2*)&Ah[row * PADA + c4] = hi;
            *(uint2*)&Al[row * PADA + c4] = lo;
        }
        // load + split B tile 32x128
#pragma unroll
        for (int i = 0; i < 4; i++) {
            int idx = t + (i << 8);
            int row = idx >> 5, c4 = (idx & 31) << 2;
            float4 v = *(const float4*)(Bg + (size_t)(k0 + row) * N + c4);
            uint2 hi, lo;
            split4(v, hi, lo);
            *(uint2*)&Bh[row * PADB + c4] = hi;
            *(uint2*)&Bl[row * PADB + c4] = lo;
        }
        __syncthreads();

#pragma unroll
        for (int ks = 0; ks < 32; ks += 16) {
#pragma unroll
            for (int p = 0; p < 3; p++) {
                unsigned int abase = ((p == 2) ? aL : aH) + (unsigned int)(ks * 2);
                unsigned int bbase = ((p == 1) ? bL : bH) + (unsigned int)(ks * PADB * 2);
                unsigned int afr[4][4];
                unsigned int bfr[4][2];
#pragma unroll
                for (int mi = 0; mi < 4; mi++)
                    ldsm_x4(afr[mi], abase + (unsigned int)(mi * 16 * PADA * 2));
#pragma unroll
                for (int ni = 0; ni < 4; ni++)
                    ldsm_x2t(bfr[ni], bbase + (unsigned int)(ni * 16));
#pragma unroll
                for (int mi = 0; mi < 4; mi++)
#pragma unroll
                    for (int ni = 0; ni < 4; ni++)
                        mma_bf16(acc[mi][ni], afr[mi], bfr[ni]);
            }
        }
        __syncthreads();
    }

    // epilogue
#pragma unroll
    for (int mi = 0; mi < 4; mi++) {
        int rbase = bm + wm + mi * 16 + (lane >> 2);
#pragma unroll
        for (int ni = 0; ni < 4; ni++) {
            int c = bn + wn + ni * 8 + ((lane & 3) << 1);
#pragma unroll
            for (int hh = 0; hh < 2; hh++) {
                int r = rbase + (hh << 3);
                float2 v = make_float2(acc[mi][ni][hh * 2], acc[mi][ni][hh * 2 + 1]);
                if (EPI == 1) {
                    float2 bs = *(const float2*)&bias[c];
                    float2 rr = *(const float2*)&res[(size_t)r * N + c];
                    v.x += bs.x + rr.x;
                    v.y += bs.y + rr.y;
                }
                if (EPI == 2) {
                    float2 bs = *(const float2*)&bias[c];
                    v.x += bs.x;
                    v.y += bs.y;
                    const float rs2i = 0.70710678118654752f;
                    v.x = 0.5f * v.x * (1.0f + erff(v.x * rs2i));
                    v.y = 0.5f * v.y * (1.0f + erff(v.y * rs2i));
                }
                *(float2*)&C[(size_t)r * N + c] = v;
            }
        }
    }
}

// ---------------- fused flash attention ------------------------------------
// CTA = (qblock 0..15, head 0..11, batch 0..7). 64 queries x Dh=64 per CTA,
// streams 16 key blocks of 64. P tile aliases K tile (stride 65 padded).
__global__ void __launch_bounds__(256) attn_kernel() {
    extern __shared__ float sm[];
    float* Qs  = sm;          // [64][64]  stride 64
    float* KPs = sm + 4096;   // [64][65]  stride 65 (K tile, then P tile)
    float* Vs  = sm + 8256;   // [64][64]  stride 64

    int t  = threadIdx.x;
    int tx = t & 15, ty = t >> 4;
    int r0 = ty << 2, c0 = tx << 2;
    int qb = blockIdx.x, h = blockIdx.y, b = blockIdx.z;
    int qbase = b * SEQ + qb * 64;
    const float scale = 0.125f;   // 1/sqrt(64)

    // load Q tile
    for (int i = t; i < 1024; i += 256) {
        int row = i >> 4, d4 = (i & 15) << 2;
        float4 q4 = *(const float4*)&g_qkv[(size_t)(qbase + row) * QKVD + h * 64 + d4];
        *(float4*)&Qs[row * 64 + d4] = q4;
    }

    float o[4][4];
    float m[4], l[4];
#pragma unroll
    for (int i = 0; i < 4; i++) {
        m[i] = -1e30f; l[i] = 0.f;
#pragma unroll
        for (int j = 0; j < 4; j++) o[i][j] = 0.f;
    }

    for (int kb = 0; kb < 16; kb++) {
        int kvb = b * SEQ + kb * 64;
        __syncthreads();   // protect K/V/P reuse (and Q load on iter 0)
        for (int i = t; i < 1024; i += 256) {
            int row = i >> 4, d4 = (i & 15) << 2;
            float4 k4 = *(const float4*)&g_qkv[(size_t)(kvb + row) * QKVD + 768 + h * 64 + d4];
            float* kp = &KPs[row * 65 + d4];
            kp[0] = k4.x; kp[1] = k4.y; kp[2] = k4.z; kp[3] = k4.w;
            float4 v4 = *(const float4*)&g_qkv[(size_t)(kvb + row) * QKVD + 1536 + h * 64 + d4];
            *(float4*)&Vs[row * 64 + d4] = v4;
        }
        __syncthreads();

        // S = Q K^T (4x4 per thread)
        float s[4][4];
#pragma unroll
        for (int i = 0; i < 4; i++)
#pragma unroll
            for (int j = 0; j < 4; j++) s[i][j] = 0.f;
        for (int d = 0; d < 64; d++) {
            float qf[4], kf[4];
#pragma unroll
            for (int i = 0; i < 4; i++) qf[i] = Qs[(r0 + i) * 64 + d];
#pragma unroll
            for (int j = 0; j < 4; j++) kf[j] = KPs[(c0 + j) * 65 + d];
#pragma unroll
            for (int i = 0; i < 4; i++)
#pragma unroll
                for (int j = 0; j < 4; j++)
                    s[i][j] = fmaf(qf[i], kf[j], s[i][j]);
        }

        // online softmax (row reduction across the 16 tx lanes)
#pragma unroll
        for (int i = 0; i < 4; i++) {
#pragma unroll
            for (int j = 0; j < 4; j++) s[i][j] *= scale;
            float mx = fmaxf(fmaxf(s[i][0], s[i][1]), fmaxf(s[i][2], s[i][3]));
#pragma unroll
            for (int off = 8; off; off >>= 1)
                mx = fmaxf(mx, __shfl_xor_sync(0xffffffffu, mx, off));
            float mn = fmaxf(m[i], mx);
            float f  = __expf(m[i] - mn);
            m[i] = mn;
            float sum = 0.f;
#pragma unroll
            for (int j = 0; j < 4; j++) {
                s[i][j] = __expf(s[i][j] - mn);
                sum += s[i][j];
            }
#pragma unroll
            for (int off = 8; off; off >>= 1)
                sum += __shfl_xor_sync(0xffffffffu, sum, off);
            l[i] = l[i] * f + sum;
#pragma unroll
            for (int j = 0; j < 4; j++) o[i][j] *= f;
        }

        __syncthreads();   // all threads done reading K tile
#pragma unroll
        for (int i = 0; i < 4; i++)
#pragma unroll
            for (int j = 0; j < 4; j++)
                KPs[(r0 + i) * 65 + c0 + j] = s[i][j];
        __syncthreads();

        // O += P V
        for (int j = 0; j < 64; j++) {
            float pf[4];
#pragma unroll
            for (int i = 0; i < 4; i++) pf[i] = KPs[(r0 + i) * 65 + j];
            float4 v4 = *(const float4*)&Vs[j * 64 + c0];
#pragma unroll
            for (int i = 0; i < 4; i++) {
                o[i][0] = fmaf(pf[i], v4.x, o[i][0]);
                o[i][1] = fmaf(pf[i], v4.y, o[i][1]);
                o[i][2] = fmaf(pf[i], v4.z, o[i][2]);
                o[i][3] = fmaf(pf[i], v4.w, o[i][3]);
            }
        }
    }

#pragma unroll
    for (int i = 0; i < 4; i++) {
        float inv = 1.0f / l[i];
        float4 v;
        v.x = o[i][0] * inv; v.y = o[i][1] * inv;
        v.z = o[i][2] * inv; v.w = o[i][3] * inv;
        *(float4*)&g_ao[(size_t)(qbase + r0 + i) * DIMC + h * 64 + c0] = v;
    }
}

// ---------------- launch -----------------------------------------------------
extern "C" void kernel_launch(void* const* d_in, const int* in_sizes, int n_in,
                              void* d_out, int out_size) {
    (void)in_sizes; (void)n_in; (void)out_size;
    const float* x     = (const float*)d_in[0];
    const float* ln1_g = (const float*)d_in[1];
    const float* ln1_b = (const float*)d_in[2];
    const float* w_qkv = (const float*)d_in[3];
    const float* w_out = (const float*)d_in[4];
    const float* b_out = (const float*)d_in[5];
    const float* ln2_g = (const float*)d_in[6];
    const float* ln2_b = (const float*)d_in[7];
    const float* w1    = (const float*)d_in[8];
    const float* b1    = (const float*)d_in[9];
    const float* w2    = (const float*)d_in[10];
    const float* b2    = (const float*)d_in[11];
    float* out = (float*)d_out;

    float *h1, *qkv, *ao, *x2, *h2, *act;
    cudaGetSymbolAddress((void**)&h1,  g_h1);
    cudaGetSymbolAddress((void**)&qkv, g_qkv);
    cudaGetSymbolAddress((void**)&ao,  g_ao);
    cudaGetSymbolAddress((void**)&x2,  g_x2);
    cudaGetSymbolAddress((void**)&h2,  g_h2);
    cudaGetSymbolAddress((void**)&act, g_act);

    cudaFuncSetAttribute(attn_kernel,
                         cudaFuncAttributeMaxDynamicSharedMemorySize, 49408);

    // 1) h1 = LN1(x)
    ln_kernel<<<TOK, 256>>>(x, ln1_g, ln1_b, h1);
    // 2) qkv = h1 @ w_qkv              (8192 x 2304 x 768)
    mma_gemm<0><<<dim3(QKVD / 128, TOK / 128), 256>>>(
        h1, w_qkv, qkv, TOK, QKVD, DIMC, (const float*)0, (const float*)0);
    // 3) fused attention -> g_ao
    attn_kernel<<<dim3(16, 12, 8), 256, 49408>>>();
    // 4) x2 = x + ao @ w_out + b_out   (8192 x 768 x 768)
    mma_gemm<1><<<dim3(DIMC / 128, TOK / 128), 256>>>(
        ao, w_out, x2, TOK, DIMC, DIMC, b_out, x);
    // 5) h2 = LN2(x2)
    ln_kernel<<<TOK, 256>>>(x2, ln2_g, ln2_b, h2);
    // 6) act = gelu(h2 @ w1 + b1)      (8192 x 3072 x 768)
    mma_gemm<2><<<dim3(MLPD / 128, TOK / 128), 256>>>(
        h2, w1, act, TOK, MLPD, DIMC, b1, (const float*)0);
    // 7) out = x2 + act @ w2 + b2      (8192 x 768 x 3072)
    mma_gemm<1><<<dim3(DIMC / 128, TOK / 128), 256>>>(
        act, w2, out, TOK, DIMC, MLPD, b2, x2);
}

// round 14
// speedup vs baseline: 1.9812x; 1.0301x over previous
#include <cuda_runtime.h>
#include <cuda_bf16.h>
#include <stdint.h>
#include <cstdint>
#include <math.h>

#define TOK   8192        // 8 * 1024 tokens
#define DIMC  768
#define QKVD  2304
#define MLPD  3072
#define SEQ   1024

#define PADA  40          // A smem row stride (bf16): ldmatrix conflict-free
#define PADB  136         // B smem row stride (bf16): ldmatrix conflict-free
#define A_ELE (128 * PADA)            // 5120 bf16
#define B_ELE (32 * PADB)             // 4352 bf16
#define STAGE_BYTES ((2 * A_ELE + 2 * B_ELE) * 2)   // 37888
#define SMEM_TOTAL  (2 * STAGE_BYTES)               // 75776

// ---------------- scratch (device globals: no allocation allowed) ----------
__device__ float          g_qkv [TOK * QKVD];
__device__ float          g_x2  [TOK * DIMC];
__device__ __nv_bfloat16  g_h1h [TOK * DIMC],  g_h1l [TOK * DIMC];
__device__ __nv_bfloat16  g_aoh [TOK * DIMC],  g_aol [TOK * DIMC];
__device__ __nv_bfloat16  g_h2h [TOK * DIMC],  g_h2l [TOK * DIMC];
__device__ __nv_bfloat16  g_acth[TOK * MLPD],  g_actl[TOK * MLPD];
__device__ __nv_bfloat16  g_wqkvh[DIMC * QKVD], g_wqkvl[DIMC * QKVD];
__device__ __nv_bfloat16  g_wouth[DIMC * DIMC], g_woutl[DIMC * DIMC];
__device__ __nv_bfloat16  g_w1h  [DIMC * MLPD], g_w1l  [DIMC * MLPD];
__device__ __nv_bfloat16  g_w2h  [MLPD * DIMC], g_w2l  [MLPD * DIMC];

// ---------------- helpers ----------------------------------------------------
__device__ __forceinline__ unsigned int packbf(float a, float b) {
    __nv_bfloat162 t = __floats2bfloat162_rn(a, b);
    return *(unsigned int*)&t;
}
__device__ __forceinline__ void split4(float4 v, uint2& hi, uint2& lo) {
    float hx = __bfloat162float(__float2bfloat16(v.x));
    float hy = __bfloat162float(__float2bfloat16(v.y));
    float hz = __bfloat162float(__float2bfloat16(v.z));
    float hw = __bfloat162float(__float2bfloat16(v.w));
    hi.x = packbf(hx, hy);
    hi.y = packbf(hz, hw);
    lo.x = packbf(v.x - hx, v.y - hy);
    lo.y = packbf(v.z - hz, v.w - hw);
}
__device__ __forceinline__ void ldsm_x4(unsigned int* r, unsigned int addr) {
    asm volatile("ldmatrix.sync.aligned.m8n8.x4.shared.b16 {%0,%1,%2,%3}, [%4];"
                 : "=r"(r[0]), "=r"(r[1]), "=r"(r[2]), "=r"(r[3]) : "r"(addr));
}
__device__ __forceinline__ void ldsm_x2t(unsigned int* r, unsigned int addr) {
    asm volatile("ldmatrix.sync.aligned.m8n8.x2.trans.shared.b16 {%0,%1}, [%2];"
                 : "=r"(r[0]), "=r"(r[1]) : "r"(addr));
}
__device__ __forceinline__ void mma_bf16(float* d, const unsigned int* a,
                                         const unsigned int* b) {
    asm volatile(
        "mma.sync.aligned.m16n8k16.row.col.f32.bf16.bf16.f32 "
        "{%0,%1,%2,%3}, {%4,%5,%6,%7}, {%8,%9}, {%0,%1,%2,%3};"
        : "+f"(d[0]), "+f"(d[1]), "+f"(d[2]), "+f"(d[3])
        : "r"(a[0]), "r"(a[1]), "r"(a[2]), "r"(a[3]), "r"(b[0]), "r"(b[1]));
}
__device__ __forceinline__ void cpa16(unsigned int dst, const void* src) {
    asm volatile("cp.async.cg.shared.global [%0], [%1], 16;" :: "r"(dst), "l"(src));
}

// ---------------- weight split: fp32 -> bf16 hi/lo ---------------------------
__global__ void __launch_bounds__(256) split_kernel(const float* __restrict__ w,
                                                    __nv_bfloat16* __restrict__ hi,
                                                    __nv_bfloat16* __restrict__ lo) {
    int i = (blockIdx.x * 256 + threadIdx.x) * 4;
    float4 v = *(const float4*)(w + i);
    uint2 h, l;
    split4(v, h, l);
    *(uint2*)&hi[i] = h;
    *(uint2*)&lo[i] = l;
}

// ---------------- LayerNorm -> bf16 hi/lo ------------------------------------
__global__ void __launch_bounds__(256) ln_kernel(const float* __restrict__ x,
                                                 const float* __restrict__ g,
                                                 const float* __restrict__ b,
                                                 __nv_bfloat16* __restrict__ oh,
                                                 __nv_bfloat16* __restrict__ ol) {
    int row = blockIdx.x;
    int t = threadIdx.x;
    const float* xr = x + (size_t)row * DIMC;
    float v0 = xr[t], v1 = xr[t + 256], v2 = xr[t + 512];
    float s  = v0 + v1 + v2;
    float s2 = v0 * v0 + v1 * v1 + v2 * v2;
#pragma unroll
    for (int off = 16; off; off >>= 1) {
        s  += __shfl_xor_sync(0xffffffffu, s,  off);
        s2 += __shfl_xor_sync(0xffffffffu, s2, off);
    }
    __shared__ float rs[8], rs2[8];
    int w = t >> 5;
    if ((t & 31) == 0) { rs[w] = s; rs2[w] = s2; }
    __syncthreads();
    s = 0.f; s2 = 0.f;
#pragma unroll
    for (int i = 0; i < 8; i++) { s += rs[i]; s2 += rs2[i]; }
    float mu   = s  * (1.0f / DIMC);
    float var  = s2 * (1.0f / DIMC) - mu * mu;
    float rstd = rsqrtf(var + 1e-5f);
#pragma unroll
    for (int j = 0; j < 3; j++) {
        int c = t + (j << 8);
        float v = (j == 0) ? v0 : (j == 1) ? v1 : v2;
        float y = (v - mu) * rstd * g[c] + b[c];
        __nv_bfloat16 hb = __float2bfloat16(y);
        oh[(size_t)row * DIMC + c] = hb;
        ol[(size_t)row * DIMC + c] = __float2bfloat16(y - __bfloat162float(hb));
    }
}

// ---------------- split-bf16 tensor-core GEMM, cp.async double-buffered ------
// C(MxN) = A(MxK) @ B(KxN); A,B given pre-split as bf16 hi/lo pairs.
// acc = Ah*Bh + Ah*Bl + Al*Bh (fp32).  CTA tile 128x128, K-tile 32, 8 warps.
// EPI 0: C fp32 = AB
// EPI 1: C fp32 = AB + bias[n] + res[m][n]
// EPI 2: Ch/Cl bf16 split = gelu_exact(AB + bias[n])
template <int EPI>
__global__ void __launch_bounds__(256, 2) mma_gemm(
    const __nv_bfloat16* __restrict__ Agh, const __nv_bfloat16* __restrict__ Agl,
    const __nv_bfloat16* __restrict__ Bgh, const __nv_bfloat16* __restrict__ Bgl,
    float* __restrict__ C, __nv_bfloat16* __restrict__ Ch, __nv_bfloat16* __restrict__ Cl,
    int M, int N, int K,
    const float* __restrict__ bias, const float* __restrict__ res) {
    extern __shared__ __nv_bfloat16 sm_bf[];
    unsigned int smem_u = (unsigned int)__cvta_generic_to_shared(sm_bf);

    int t = threadIdx.x;
    int lane = t & 31, wid = t >> 5;
    int wm = (wid >> 2) << 6;
    int wn = (wid & 3) << 5;
    int bm = blockIdx.y << 7, bn = blockIdx.x << 7;

    const __nv_bfloat16* Ah_g = Agh + (size_t)bm * K;
    const __nv_bfloat16* Al_g = Agl + (size_t)bm * K;
    const __nv_bfloat16* Bh_g = Bgh + bn;
    const __nv_bfloat16* Bl_g = Bgl + bn;

    float acc[4][4][4];
#pragma unroll
    for (int mi = 0; mi < 4; mi++)
#pragma unroll
        for (int ni = 0; ni < 4; ni++)
#pragma unroll
            for (int k = 0; k < 4; k++) acc[mi][ni][k] = 0.f;

    // per-lane fragment offsets (bytes, within a stage)
    unsigned int aoff = (unsigned int)(((wm + (lane & 15)) * PADA + ((lane >> 4) << 3)) * 2);
    unsigned int boff = (unsigned int)(((lane & 15) * PADB + wn) * 2);

    // per-thread cp.async chunk coordinates
    int ar0 = t >> 2,  ac0 = (t & 3) << 3;            // A: chunks t, t+256
    int ar1 = (t + 256) >> 2, ac1 = ((t + 256) & 3) << 3;
    int br0 = t >> 4,  bc0 = (t & 15) << 3;           // B: chunks t, t+256
    int br1 = (t + 256) >> 4, bc1 = ((t + 256) & 15) << 3;

#define LOAD_STAGE(SB, K0)                                                         \
    do {                                                                           \
        unsigned int aH = (SB), aL = (SB) + A_ELE * 2;                             \
        unsigned int bH = (SB) + 4 * A_ELE, bL = bH + B_ELE * 2;                   \
        cpa16(aH + (unsigned int)(ar0 * PADA + ac0) * 2, Ah_g + (size_t)ar0 * K + (K0) + ac0); \
        cpa16(aH + (unsigned int)(ar1 * PADA + ac1) * 2, Ah_g + (size_t)ar1 * K + (K0) + ac1); \
        cpa16(aL + (unsigned int)(ar0 * PADA + ac0) * 2, Al_g + (size_t)ar0 * K + (K0) + ac0); \
        cpa16(aL + (unsigned int)(ar1 * PADA + ac1) * 2, Al_g + (size_t)ar1 * K + (K0) + ac1); \
        cpa16(bH + (unsigned int)(br0 * PADB + bc0) * 2, Bh_g + (size_t)((K0) + br0) * N + bc0); \
        cpa16(bH + (unsigned int)(br1 * PADB + bc1) * 2, Bh_g + (size_t)((K0) + br1) * N + bc1); \
        cpa16(bL + (unsigned int)(br0 * PADB + bc0) * 2, Bl_g + (size_t)((K0) + br0) * N + bc0); \
        cpa16(bL + (unsigned int)(br1 * PADB + bc1) * 2, Bl_g + (size_t)((K0) + br1) * N + bc1); \
        asm volatile("cp.async.commit_group;");                                    \
    } while (0)

    int nk = K >> 5;
    LOAD_STAGE(smem_u, 0);

    for (int kt = 0; kt < nk; kt++) {
        unsigned int cur = smem_u + (unsigned int)(kt & 1) * STAGE_BYTES;
        if (kt + 1 < nk) {
            unsigned int nxt = smem_u + (unsigned int)((kt + 1) & 1) * STAGE_BYTES;
            LOAD_STAGE(nxt, (kt + 1) << 5);
            asm volatile("cp.async.wait_group 1;");
        } else {
            asm volatile("cp.async.wait_group 0;");
        }
        __syncthreads();

        unsigned int baseAh = cur + aoff;
        unsigned int baseAl = baseAh + A_ELE * 2;
        unsigned int baseBh = cur + 4 * A_ELE + boff;
        unsigned int baseBl = baseBh + B_ELE * 2;

#pragma unroll
        for (int ks = 0; ks < 32; ks += 16) {
            unsigned int ah[4][4], al[4][4], bf[4][2];
#pragma unroll
            for (int mi = 0; mi < 4; mi++)
                ldsm_x4(ah[mi], baseAh + (unsigned int)(ks * 2 + mi * 16 * PADA * 2));
#pragma unroll
            for (int mi = 0; mi < 4; mi++)
                ldsm_x4(al[mi], baseAl + (unsigned int)(ks * 2 + mi * 16 * PADA * 2));
            // B hi: used by Ah and Al passes
#pragma unroll
            for (int ni = 0; ni < 4; ni++)
                ldsm_x2t(bf[ni], baseBh + (unsigned int)(ks * PADB * 2 + ni * 16));
#pragma unroll
            for (int mi = 0; mi < 4; mi++)
#pragma unroll
                for (int ni = 0; ni < 4; ni++)
                    mma_bf16(acc[mi][ni], ah[mi], bf[ni]);
#pragma unroll
            for (int mi = 0; mi < 4; mi++)
#pragma unroll
                for (int ni = 0; ni < 4; ni++)
                    mma_bf16(acc[mi][ni], al[mi], bf[ni]);
            // B lo: only Ah pass
#pragma unroll
            for (int ni = 0; ni < 4; ni++)
                ldsm_x2t(bf[ni], baseBl + (unsigned int)(ks * PADB * 2 + ni * 16));
#pragma unroll
            for (int mi = 0; mi < 4; mi++)
#pragma unroll
                for (int ni = 0; ni < 4; ni++)
                    mma_bf16(acc[mi][ni], ah[mi], bf[ni]);
        }
        __syncthreads();
    }

    // epilogue
#pragma unroll
    for (int mi = 0; mi < 4; mi++) {
        int rbase = bm + wm + mi * 16 + (lane >> 2);
#pragma unroll
        for (int ni = 0; ni < 4; ni++) {
            int c = bn + wn + ni * 8 + ((lane & 3) << 1);
#pragma unroll
            for (int hh = 0; hh < 2; hh++) {
                int r = rbase + (hh << 3);
                float2 v = make_float2(acc[mi][ni][hh * 2], acc[mi][ni][hh * 2 + 1]);
                if (EPI == 0) {
                    *(float2*)&C[(size_t)r * N + c] = v;
                }
                if (EPI == 1) {
                    float2 bs = *(const float2*)&bias[c];
                    float2 rr = *(const float2*)&res[(size_t)r * N + c];
                    v.x += bs.x + rr.x;
                    v.y += bs.y + rr.y;
                    *(float2*)&C[(size_t)r * N + c] = v;
                }
                if (EPI == 2) {
                    float2 bs = *(const float2*)&bias[c];
                    v.x += bs.x;
                    v.y += bs.y;
                    const float rs2i = 0.70710678118654752f;
                    v.x = 0.5f * v.x * (1.0f + erff(v.x * rs2i));
                    v.y = 0.5f * v.y * (1.0f + erff(v.y * rs2i));
                    float hx = __bfloat162float(__float2bfloat16(v.x));
                    float hy = __bfloat162float(__float2bfloat16(v.y));
                    *(unsigned int*)&Ch[(size_t)r * N + c] = packbf(hx, hy);
                    *(unsigned int*)&Cl[(size_t)r * N + c] = packbf(v.x - hx, v.y - hy);
                }
            }
        }
    }
}

// ---------------- fused flash attention (fp32, writes split bf16) ------------
__global__ void __launch_bounds__(256) attn_kernel() {
    extern __shared__ float sm[];
    float* Qs  = sm;          // [64][64]
    float* KPs = sm + 4096;   // [64][65]
    float* Vs  = sm + 8256;   // [64][64]

    int t  = threadIdx.x;
    int tx = t & 15, ty = t >> 4;
    int r0 = ty << 2, c0 = tx << 2;
    int qb = blockIdx.x, h = blockIdx.y, b = blockIdx.z;
    int qbase = b * SEQ + qb * 64;
    const float scale = 0.125f;

    for (int i = t; i < 1024; i += 256) {
        int row = i >> 4, d4 = (i & 15) << 2;
        float4 q4 = *(const float4*)&g_qkv[(size_t)(qbase + row) * QKVD + h * 64 + d4];
        *(float4*)&Qs[row * 64 + d4] = q4;
    }

    float o[4][4];
    float m[4], l[4];
#pragma unroll
    for (int i = 0; i < 4; i++) {
        m[i] = -1e30f; l[i] = 0.f;
#pragma unroll
        for (int j = 0; j < 4; j++) o[i][j] = 0.f;
    }

    for (int kb = 0; kb < 16; kb++) {
        int kvb = b * SEQ + kb * 64;
        __syncthreads();
        for (int i = t; i < 1024; i += 256) {
            int row = i >> 4, d4 = (i & 15) << 2;
            float4 k4 = *(const float4*)&g_qkv[(size_t)(kvb + row) * QKVD + 768 + h * 64 + d4];
            float* kp = &KPs[row * 65 + d4];
            kp[0] = k4.x; kp[1] = k4.y; kp[2] = k4.z; kp[3] = k4.w;
            float4 v4 = *(const float4*)&g_qkv[(size_t)(kvb + row) * QKVD + 1536 + h * 64 + d4];
            *(float4*)&Vs[row * 64 + d4] = v4;
        }
        __syncthreads();

        float s[4][4];
#pragma unroll
        for (int i = 0; i < 4; i++)
#pragma unroll
            for (int j = 0; j < 4; j++) s[i][j] = 0.f;
        for (int d = 0; d < 64; d++) {
            float qf[4], kf[4];
#pragma unroll
            for (int i = 0; i < 4; i++) qf[i] = Qs[(r0 + i) * 64 + d];
#pragma unroll
            for (int j = 0; j < 4; j++) kf[j] = KPs[(c0 + j) * 65 + d];
#pragma unroll
            for (int i = 0; i < 4; i++)
#pragma unroll
                for (int j = 0; j < 4; j++)
                    s[i][j] = fmaf(qf[i], kf[j], s[i][j]);
        }

#pragma unroll
        for (int i = 0; i < 4; i++) {
#pragma unroll
            for (int j = 0; j < 4; j++) s[i][j] *= scale;
            float mx = fmaxf(fmaxf(s[i][0], s[i][1]), fmaxf(s[i][2], s[i][3]));
#pragma unroll
            for (int off = 8; off; off >>= 1)
                mx = fmaxf(mx, __shfl_xor_sync(0xffffffffu, mx, off));
            float mn = fmaxf(m[i], mx);
            float f  = __expf(m[i] - mn);
            m[i] = mn;
            float sum = 0.f;
#pragma unroll
            for (int j = 0; j < 4; j++) {
                s[i][j] = __expf(s[i][j] - mn);
                sum += s[i][j];
            }
#pragma unroll
            for (int off = 8; off; off >>= 1)
                sum += __shfl_xor_sync(0xffffffffu, sum, off);
            l[i] = l[i] * f + sum;
#pragma unroll
            for (int j = 0; j < 4; j++) o[i][j] *= f;
        }

        __syncthreads();
#pragma unroll
        for (int i = 0; i < 4; i++)
#pragma unroll
            for (int j = 0; j < 4; j++)
                KPs[(r0 + i) * 65 + c0 + j] = s[i][j];
        __syncthreads();

        for (int j = 0; j < 64; j++) {
            float pf[4];
#pragma unroll
            for (int i = 0; i < 4; i++) pf[i] = KPs[(r0 + i) * 65 + j];
            float4 v4 = *(const float4*)&Vs[j * 64 + c0];
#pragma unroll
            for (int i = 0; i < 4; i++) {
                o[i][0] = fmaf(pf[i], v4.x, o[i][0]);
                o[i][1] = fmaf(pf[i], v4.y, o[i][1]);
                o[i][2] = fmaf(pf[i], v4.z, o[i][2]);
                o[i][3] = fmaf(pf[i], v4.w, o[i][3]);
            }
        }
    }

#pragma unroll
    for (int i = 0; i < 4; i++) {
        float inv = 1.0f / l[i];
        float4 v;
        v.x = o[i][0] * inv; v.y = o[i][1] * inv;
        v.z = o[i][2] * inv; v.w = o[i][3] * inv;
        uint2 hi, lo;
        split4(v, hi, lo);
        size_t idx = (size_t)(qbase + r0 + i) * DIMC + h * 64 + c0;
        *(uint2*)&g_aoh[idx] = hi;
        *(uint2*)&g_aol[idx] = lo;
    }
}

// ---------------- launch -----------------------------------------------------
extern "C" void kernel_launch(void* const* d_in, const int* in_sizes, int n_in,
                              void* d_out, int out_size) {
    (void)in_sizes; (void)n_in; (void)out_size;
    const float* x     = (const float*)d_in[0];
    const float* ln1_g = (const float*)d_in[1];
    const float* ln1_b = (const float*)d_in[2];
    const float* w_qkv = (const float*)d_in[3];
    const float* w_out = (const float*)d_in[4];
    const float* b_out = (const float*)d_in[5];
    const float* ln2_g = (const float*)d_in[6];
    const float* ln2_b = (const float*)d_in[7];
    const float* w1    = (const float*)d_in[8];
    const float* b1    = (const float*)d_in[9];
    const float* w2    = (const float*)d_in[10];
    const float* b2    = (const float*)d_in[11];
    float* out = (float*)d_out;

    float *qkv, *x2;
    __nv_bfloat16 *h1h, *h1l, *aoh, *aol, *h2h, *h2l, *acth, *actl;
    __nv_bfloat16 *wqkvh, *wqkvl, *wouth, *woutl, *w1h, *w1l, *w2h, *w2l;
    cudaGetSymbolAddress((void**)&qkv,  g_qkv);
    cudaGetSymbolAddress((void**)&x2,   g_x2);
    cudaGetSymbolAddress((void**)&h1h,  g_h1h);  cudaGetSymbolAddress((void**)&h1l,  g_h1l);
    cudaGetSymbolAddress((void**)&aoh,  g_aoh);  cudaGetSymbolAddress((void**)&aol,  g_aol);
    cudaGetSymbolAddress((void**)&h2h,  g_h2h);  cudaGetSymbolAddress((void**)&h2l,  g_h2l);
    cudaGetSymbolAddress((void**)&acth, g_acth); cudaGetSymbolAddress((void**)&actl, g_actl);
    cudaGetSymbolAddress((void**)&wqkvh, g_wqkvh); cudaGetSymbolAddress((void**)&wqkvl, g_wqkvl);
    cudaGetSymbolAddress((void**)&wouth, g_wouth); cudaGetSymbolAddress((void**)&woutl, g_woutl);
    cudaGetSymbolAddress((void**)&w1h, g_w1h); cudaGetSymbolAddress((void**)&w1l, g_w1l);
    cudaGetSymbolAddress((void**)&w2h, g_w2h); cudaGetSymbolAddress((void**)&w2l, g_w2l);

    cudaFuncSetAttribute(attn_kernel,
                         cudaFuncAttributeMaxDynamicSharedMemorySize, 49408);
    cudaFuncSetAttribute(mma_gemm<0>,
                         cudaFuncAttributeMaxDynamicSharedMemorySize, SMEM_TOTAL);
    cudaFuncSetAttribute(mma_gemm<1>,
                         cudaFuncAttributeMaxDynamicSharedMemorySize, SMEM_TOTAL);
    cudaFuncSetAttribute(mma_gemm<2>,
                         cudaFuncAttributeMaxDynamicSharedMemorySize, SMEM_TOTAL);

    // 0) split weights to bf16 hi/lo
    split_kernel<<<(DIMC * QKVD) / 1024, 256>>>(w_qkv, wqkvh, wqkvl);
    split_kernel<<<(DIMC * DIMC) / 1024, 256>>>(w_out, wouth, woutl);
    split_kernel<<<(DIMC * MLPD) / 1024, 256>>>(w1, w1h, w1l);
    split_kernel<<<(MLPD * DIMC) / 1024, 256>>>(w2, w2h, w2l);

    // 1) h1 = LN1(x)   (split bf16)
    ln_kernel<<<TOK, 256>>>(x, ln1_g, ln1_b, h1h, h1l);
    // 2) qkv = h1 @ w_qkv   (fp32 out)
    mma_gemm<0><<<dim3(QKVD / 128, TOK / 128), 256, SMEM_TOTAL>>>(
        h1h, h1l, wqkvh, wqkvl, qkv, (__nv_bfloat16*)0, (__nv_bfloat16*)0,
        TOK, QKVD, DIMC, (const float*)0, (const float*)0);
    // 3) attention -> ao (split bf16)
    attn_kernel<<<dim3(16, 12, 8), 256, 49408>>>();
    // 4) x2 = x + ao @ w_out + b_out   (fp32)
    mma_gemm<1><<<dim3(DIMC / 128, TOK / 128), 256, SMEM_TOTAL>>>(
        aoh, aol, wouth, woutl, x2, (__nv_bfloat16*)0, (__nv_bfloat16*)0,
        TOK, DIMC, DIMC, b_out, x);
    // 5) h2 = LN2(x2)   (split bf16)
    ln_kernel<<<TOK, 256>>>(x2, ln2_g, ln2_b, h2h, h2l);
    // 6) act = gelu(h2 @ w1 + b1)   (split bf16)
    mma_gemm<2><<<dim3(MLPD / 128, TOK / 128), 256, SMEM_TOTAL>>>(
        h2h, h2l, w1h, w1l, (float*)0, acth, actl,
        TOK, MLPD, DIMC, b1, (const float*)0);
    // 7) out = x2 + act @ w2 + b2   (fp32)
    mma_gemm<1><<<dim3(DIMC / 128, TOK / 128), 256, SMEM_TOTAL>>>(
        acth, actl, w2h, w2l, out, (__nv_bfloat16*)0, (__nv_bfloat16*)0,
        TOK, DIMC, MLPD, b2, x2);
}

// round 15
// speedup vs baseline: 1.9821x; 1.0004x over previous
#include <cuda_runtime.h>
#include <cuda_bf16.h>
#include <stdint.h>
#include <cstdint>
#include <math.h>

#define TOK   8192        // 8 * 1024 tokens
#define DIMC  768
#define QKVD  2304
#define MLPD  3072
#define SEQ   1024

#define PADA  40          // A smem row stride (bf16): ldmatrix conflict-free
#define PADB  136         // B smem row stride (bf16): ldmatrix conflict-free
#define A_ELE (128 * PADA)            // 5120 bf16
#define B_ELE (32 * PADB)             // 4352 bf16
#define STAGE_BYTES ((2 * A_ELE + 2 * B_ELE) * 2)   // 37888
#define SMEM_TOTAL  (2 * STAGE_BYTES)               // 75776

// ---------------- scratch (device globals: no allocation allowed) ----------
__device__ float          g_qkv [TOK * QKVD];
__device__ float          g_x2  [TOK * DIMC];
__device__ __nv_bfloat16  g_h1h [TOK * DIMC],  g_h1l [TOK * DIMC];
__device__ __nv_bfloat16  g_aoh [TOK * DIMC],  g_aol [TOK * DIMC];
__device__ __nv_bfloat16  g_h2h [TOK * DIMC],  g_h2l [TOK * DIMC];
__device__ __nv_bfloat16  g_acth[TOK * MLPD],  g_actl[TOK * MLPD];
__device__ __nv_bfloat16  g_wqkvh[DIMC * QKVD], g_wqkvl[DIMC * QKVD];
__device__ __nv_bfloat16  g_wouth[DIMC * DIMC], g_woutl[DIMC * DIMC];
__device__ __nv_bfloat16  g_w1h  [DIMC * MLPD], g_w1l  [DIMC * MLPD];
__device__ __nv_bfloat16  g_w2h  [MLPD * DIMC], g_w2l  [MLPD * DIMC];

// ---------------- helpers ----------------------------------------------------
__device__ __forceinline__ unsigned int packbf(float a, float b) {
    __nv_bfloat162 t = __floats2bfloat162_rn(a, b);
    return *(unsigned int*)&t;
}
__device__ __forceinline__ void split4(float4 v, uint2& hi, uint2& lo) {
    float hx = __bfloat162float(__float2bfloat16(v.x));
    float hy = __bfloat162float(__float2bfloat16(v.y));
    float hz = __bfloat162float(__float2bfloat16(v.z));
    float hw = __bfloat162float(__float2bfloat16(v.w));
    hi.x = packbf(hx, hy);
    hi.y = packbf(hz, hw);
    lo.x = packbf(v.x - hx, v.y - hy);
    lo.y = packbf(v.z - hz, v.w - hw);
}
__device__ __forceinline__ void ldsm_x4(unsigned int* r, unsigned int addr) {
    asm volatile("ldmatrix.sync.aligned.m8n8.x4.shared.b16 {%0,%1,%2,%3}, [%4];"
                 : "=r"(r[0]), "=r"(r[1]), "=r"(r[2]), "=r"(r[3]) : "r"(addr));
}
__device__ __forceinline__ void ldsm_x2t(unsigned int* r, unsigned int addr) {
    asm volatile("ldmatrix.sync.aligned.m8n8.x2.trans.shared.b16 {%0,%1}, [%2];"
                 : "=r"(r[0]), "=r"(r[1]) : "r"(addr));
}
__device__ __forceinline__ void mma_bf16(float* d, const unsigned int* a,
                                         const unsigned int* b) {
    asm volatile(
        "mma.sync.aligned.m16n8k16.row.col.f32.bf16.bf16.f32 "
        "{%0,%1,%2,%3}, {%4,%5,%6,%7}, {%8,%9}, {%0,%1,%2,%3};"
        : "+f"(d[0]), "+f"(d[1]), "+f"(d[2]), "+f"(d[3])
        : "r"(a[0]), "r"(a[1]), "r"(a[2]), "r"(a[3]), "r"(b[0]), "r"(b[1]));
}
__device__ __forceinline__ void cpa16(unsigned int dst, const void* src) {
    asm volatile("cp.async.cg.shared.global [%0], [%1], 16;" :: "r"(dst), "l"(src));
}

// ---------------- weight split: fp32 -> bf16 hi/lo ---------------------------
__global__ void __launch_bounds__(256) split_kernel(const float* __restrict__ w,
                                                    __nv_bfloat16* __restrict__ hi,
                                                    __nv_bfloat16* __restrict__ lo) {
    int i = (blockIdx.x * 256 + threadIdx.x) * 4;
    float4 v = *(const float4*)(w + i);
    uint2 h, l;
    split4(v, h, l);
    *(uint2*)&hi[i] = h;
    *(uint2*)&lo[i] = l;
}

// ---------------- LayerNorm -> bf16 hi/lo ------------------------------------
__global__ void __launch_bounds__(256) ln_kernel(const float* __restrict__ x,
                                                 const float* __restrict__ g,
                                                 const float* __restrict__ b,
                                                 __nv_bfloat16* __restrict__ oh,
                                                 __nv_bfloat16* __restrict__ ol) {
    int row = blockIdx.x;
    int t = threadIdx.x;
    const float* xr = x + (size_t)row * DIMC;
    float v0 = xr[t], v1 = xr[t + 256], v2 = xr[t + 512];
    float s  = v0 + v1 + v2;
    float s2 = v0 * v0 + v1 * v1 + v2 * v2;
#pragma unroll
    for (int off = 16; off; off >>= 1) {
        s  += __shfl_xor_sync(0xffffffffu, s,  off);
        s2 += __shfl_xor_sync(0xffffffffu, s2, off);
    }
    __shared__ float rs[8], rs2[8];
    int w = t >> 5;
    if ((t & 31) == 0) { rs[w] = s; rs2[w] = s2; }
    __syncthreads();
    s = 0.f; s2 = 0.f;
#pragma unroll
    for (int i = 0; i < 8; i++) { s += rs[i]; s2 += rs2[i]; }
    float mu   = s  * (1.0f / DIMC);
    float var  = s2 * (1.0f / DIMC) - mu * mu;
    float rstd = rsqrtf(var + 1e-5f);
#pragma unroll
    for (int j = 0; j < 3; j++) {
        int c = t + (j << 8);
        float v = (j == 0) ? v0 : (j == 1) ? v1 : v2;
        float y = (v - mu) * rstd * g[c] + b[c];
        __nv_bfloat16 hb = __float2bfloat16(y);
        oh[(size_t)row * DIMC + c] = hb;
        ol[(size_t)row * DIMC + c] = __float2bfloat16(y - __bfloat162float(hb));
    }
}

// ---------------- split-bf16 tensor-core GEMM, cp.async double-buffered ------
// C(MxN) = A(MxK) @ B(KxN); A,B given pre-split as bf16 hi/lo pairs.
// acc = Ah*Bh + Ah*Bl + Al*Bh (fp32).  CTA tile 128x128, K-tile 32, 8 warps.
// EPI 0: C fp32 = AB
// EPI 1: C fp32 = AB + bias[n] + res[m][n]
// EPI 2: Ch/Cl bf16 split = gelu_exact(AB + bias[n])
template <int EPI>
__global__ void __launch_bounds__(256, 2) mma_gemm(
    const __nv_bfloat16* __restrict__ Agh, const __nv_bfloat16* __restrict__ Agl,
    const __nv_bfloat16* __restrict__ Bgh, const __nv_bfloat16* __restrict__ Bgl,
    float* __restrict__ C, __nv_bfloat16* __restrict__ Ch, __nv_bfloat16* __restrict__ Cl,
    int M, int N, int K,
    const float* __restrict__ bias, const float* __restrict__ res) {
    extern __shared__ __nv_bfloat16 sm_bf[];
    unsigned int smem_u = (unsigned int)__cvta_generic_to_shared(sm_bf);

    int t = threadIdx.x;
    int lane = t & 31, wid = t >> 5;
    int wm = (wid >> 2) << 6;
    int wn = (wid & 3) << 5;
    int bm = blockIdx.y << 7, bn = blockIdx.x << 7;

    const __nv_bfloat16* Ah_g = Agh + (size_t)bm * K;
    const __nv_bfloat16* Al_g = Agl + (size_t)bm * K;
    const __nv_bfloat16* Bh_g = Bgh + bn;
    const __nv_bfloat16* Bl_g = Bgl + bn;

    float acc[4][4][4];
#pragma unroll
    for (int mi = 0; mi < 4; mi++)
#pragma unroll
        for (int ni = 0; ni < 4; ni++)
#pragma unroll
            for (int k = 0; k < 4; k++) acc[mi][ni][k] = 0.f;

    // per-lane fragment offsets (bytes, within a stage)
    unsigned int aoff = (unsigned int)(((wm + (lane & 15)) * PADA + ((lane >> 4) << 3)) * 2);
    unsigned int boff = (unsigned int)(((lane & 15) * PADB + wn) * 2);

    // per-thread cp.async chunk coordinates
    int ar0 = t >> 2,  ac0 = (t & 3) << 3;            // A: chunks t, t+256
    int ar1 = (t + 256) >> 2, ac1 = ((t + 256) & 3) << 3;
    int br0 = t >> 4,  bc0 = (t & 15) << 3;           // B: chunks t, t+256
    int br1 = (t + 256) >> 4, bc1 = ((t + 256) & 15) << 3;

#define LOAD_STAGE(SB, K0)                                                         \
    do {                                                                           \
        unsigned int aH = (SB), aL = (SB) + A_ELE * 2;                             \
        unsigned int bH = (SB) + 4 * A_ELE, bL = bH + B_ELE * 2;                   \
        cpa16(aH + (unsigned int)(ar0 * PADA + ac0) * 2, Ah_g + (size_t)ar0 * K + (K0) + ac0); \
        cpa16(aH + (unsigned int)(ar1 * PADA + ac1) * 2, Ah_g + (size_t)ar1 * K + (K0) + ac1); \
        cpa16(aL + (unsigned int)(ar0 * PADA + ac0) * 2, Al_g + (size_t)ar0 * K + (K0) + ac0); \
        cpa16(aL + (unsigned int)(ar1 * PADA + ac1) * 2, Al_g + (size_t)ar1 * K + (K0) + ac1); \
        cpa16(bH + (unsigned int)(br0 * PADB + bc0) * 2, Bh_g + (size_t)((K0) + br0) * N + bc0); \
        cpa16(bH + (unsigned int)(br1 * PADB + bc1) * 2, Bh_g + (size_t)((K0) + br1) * N + bc1); \
        cpa16(bL + (unsigned int)(br0 * PADB + bc0) * 2, Bl_g + (size_t)((K0) + br0) * N + bc0); \
        cpa16(bL + (unsigned int)(br1 * PADB + bc1) * 2, Bl_g + (size_t)((K0) + br1) * N + bc1); \
        asm volatile("cp.async.commit_group;");                                    \
    } while (0)

    int nk = K >> 5;
    LOAD_STAGE(smem_u, 0);

    for (int kt = 0; kt < nk; kt++) {
        unsigned int cur = smem_u + (unsigned int)(kt & 1) * STAGE_BYTES;
        if (kt + 1 < nk) {
            unsigned int nxt = smem_u + (unsigned int)((kt + 1) & 1) * STAGE_BYTES;
            LOAD_STAGE(nxt, (kt + 1) << 5);
            asm volatile("cp.async.wait_group 1;");
        } else {
            asm volatile("cp.async.wait_group 0;");
        }
        __syncthreads();

        unsigned int baseAh = cur + aoff;
        unsigned int baseAl = baseAh + A_ELE * 2;
        unsigned int baseBh = cur + 4 * A_ELE + boff;
        unsigned int baseBl = baseBh + B_ELE * 2;

#pragma unroll
        for (int ks = 0; ks < 32; ks += 16) {
            unsigned int ah[4][4], al[4][4], bf[4][2];
#pragma unroll
            for (int mi = 0; mi < 4; mi++)
                ldsm_x4(ah[mi], baseAh + (unsigned int)(ks * 2 + mi * 16 * PADA * 2));
#pragma unroll
            for (int mi = 0; mi < 4; mi++)
                ldsm_x4(al[mi], baseAl + (unsigned int)(ks * 2 + mi * 16 * PADA * 2));
            // B hi: used by Ah and Al passes
#pragma unroll
            for (int ni = 0; ni < 4; ni++)
                ldsm_x2t(bf[ni], baseBh + (unsigned int)(ks * PADB * 2 + ni * 16));
#pragma unroll
            for (int mi = 0; mi < 4; mi++)
#pragma unroll
                for (int ni = 0; ni < 4; ni++)
                    mma_bf16(acc[mi][ni], ah[mi], bf[ni]);
#pragma unroll
            for (int mi = 0; mi < 4; mi++)
#pragma unroll
                for (int ni = 0; ni < 4; ni++)
                    mma_bf16(acc[mi][ni], al[mi], bf[ni]);
            // B lo: only Ah pass
#pragma unroll
            for (int ni = 0; ni < 4; ni++)
                ldsm_x2t(bf[ni], baseBl + (unsigned int)(ks * PADB * 2 + ni * 16));
#pragma unroll
            for (int mi = 0; mi < 4; mi++)
#pragma unroll
                for (int ni = 0; ni < 4; ni++)
                    mma_bf16(acc[mi][ni], ah[mi], bf[ni]);
        }
        __syncthreads();
    }

    // epilogue
#pragma unroll
    for (int mi = 0; mi < 4; mi++) {
        int rbase = bm + wm + mi * 16 + (lane >> 2);
#pragma unroll
        for (int ni = 0; ni < 4; ni++) {
            int c = bn + wn + ni * 8 + ((lane & 3) << 1);
#pragma unroll
            for (int hh = 0; hh < 2; hh++) {
                int r = rbase + (hh << 3);
                float2 v = make_float2(acc[mi][ni][hh * 2], acc[mi][ni][hh * 2 + 1]);
                if (EPI == 0) {
                    *(float2*)&C[(size_t)r * N + c] = v;
                }
                if (EPI == 1) {
                    float2 bs = *(const float2*)&bias[c];
                    float2 rr = *(const float2*)&res[(size_t)r * N + c];
                    v.x += bs.x + rr.x;
                    v.y += bs.y + rr.y;
                    *(float2*)&C[(size_t)r * N + c] = v;
                }
                if (EPI == 2) {
                    float2 bs = *(const float2*)&bias[c];
                    v.x += bs.x;
                    v.y += bs.y;
                    const float rs2i = 0.70710678118654752f;
                    v.x = 0.5f * v.x * (1.0f + erff(v.x * rs2i));
                    v.y = 0.5f * v.y * (1.0f + erff(v.y * rs2i));
                    float hx = __bfloat162float(__float2bfloat16(v.x));
                    float hy = __bfloat162float(__float2bfloat16(v.y));
                    *(unsigned int*)&Ch[(size_t)r * N + c] = packbf(hx, hy);
                    *(unsigned int*)&Cl[(size_t)r * N + c] = packbf(v.x - hx, v.y - hy);
                }
            }
        }
    }
}

// ---------------- fused flash attention (fp32, writes split bf16) ------------
__global__ void __launch_bounds__(256) attn_kernel() {
    extern __shared__ float sm[];
    float* Qs  = sm;          // [64][64]
    float* KPs = sm + 4096;   // [64][65]
    float* Vs  = sm + 8256;   // [64][64]

    int t  = threadIdx.x;
    int tx = t & 15, ty = t >> 4;
    int r0 = ty << 2, c0 = tx << 2;
    int qb = blockIdx.x, h = blockIdx.y, b = blockIdx.z;
    int qbase = b * SEQ + qb * 64;
    const float scale = 0.125f;

    for (int i = t; i < 1024; i += 256) {
        int row = i >> 4, d4 = (i & 15) << 2;
        float4 q4 = *(const float4*)&g_qkv[(size_t)(qbase + row) * QKVD + h * 64 + d4];
        *(float4*)&Qs[row * 64 + d4] = q4;
    }

    float o[4][4];
    float m[4], l[4];
#pragma unroll
    for (int i = 0; i < 4; i++) {
        m[i] = -1e30f; l[i] = 0.f;
#pragma unroll
        for (int j = 0; j < 4; j++) o[i][j] = 0.f;
    }

    for (int kb = 0; kb < 16; kb++) {
        int kvb = b * SEQ + kb * 64;
        __syncthreads();
        for (int i = t; i < 1024; i += 256) {
            int row = i >> 4, d4 = (i & 15) << 2;
            float4 k4 = *(const float4*)&g_qkv[(size_t)(kvb + row) * QKVD + 768 + h * 64 + d4];
            float* kp = &KPs[row * 65 + d4];
            kp[0] = k4.x; kp[1] = k4.y; kp[2] = k4.z; kp[3] = k4.w;
            float4 v4 = *(const float4*)&g_qkv[(size_t)(kvb + row) * QKVD + 1536 + h * 64 + d4];
            *(float4*)&Vs[row * 64 + d4] = v4;
        }
        __syncthreads();

        float s[4][4];
#pragma unroll
        for (int i = 0; i < 4; i++)
#pragma unroll
            for (int j = 0; j < 4; j++) s[i][j] = 0.f;
        for (int d = 0; d < 64; d++) {
            float qf[4], kf[4];
#pragma unroll
            for (int i = 0; i < 4; i++) qf[i] = Qs[(r0 + i) * 64 + d];
#pragma unroll
            for (int j = 0; j < 4; j++) kf[j] = KPs[(c0 + j) * 65 + d];
#pragma unroll
            for (int i = 0; i < 4; i++)
#pragma unroll
                for (int j = 0; j < 4; j++)
                    s[i][j] = fmaf(qf[i], kf[j], s[i][j]);
        }

#pragma unroll
        for (int i = 0; i < 4; i++) {
#pragma unroll
            for (int j = 0; j < 4; j++) s[i][j] *= scale;
            float mx = fmaxf(fmaxf(s[i][0], s[i][1]), fmaxf(s[i][2], s[i][3]));
#pragma unroll
            for (int off = 8; off; off >>= 1)
                mx = fmaxf(mx, __shfl_xor_sync(0xffffffffu, mx, off));
            float mn = fmaxf(m[i], mx);
            float f  = __expf(m[i] - mn);
            m[i] = mn;
            float sum = 0.f;
#pragma unroll
            for (int j = 0; j < 4; j++) {
                s[i][j] = __expf(s[i][j] - mn);
                sum += s[i][j];
            }
#pragma unroll
            for (int off = 8; off; off >>= 1)
                sum += __shfl_xor_sync(0xffffffffu, sum, off);
            l[i] = l[i] * f + sum;
#pragma unroll
            for (int j = 0; j < 4; j++) o[i][j] *= f;
        }

        __syncthreads();
#pragma unroll
        for (int i = 0; i < 4; i++)
#pragma unroll
            for (int j = 0; j < 4; j++)
                KPs[(r0 + i) * 65 + c0 + j] = s[i][j];
        __syncthreads();

        for (int j = 0; j < 64; j++) {
            float pf[4];
#pragma unroll
            for (int i = 0; i < 4; i++) pf[i] = KPs[(r0 + i) * 65 + j];
            float4 v4 = *(const float4*)&Vs[j * 64 + c0];
#pragma unroll
            for (int i = 0; i < 4; i++) {
                o[i][0] = fmaf(pf[i], v4.x, o[i][0]);
                o[i][1] = fmaf(pf[i], v4.y, o[i][1]);
                o[i][2] = fmaf(pf[i], v4.z, o[i][2]);
                o[i][3] = fmaf(pf[i], v4.w, o[i][3]);
            }
        }
    }

#pragma unroll
    for (int i = 0; i < 4; i++) {
        float inv = 1.0f / l[i];
        float4 v;
        v.x = o[i][0] * inv; v.y = o[i][1] * inv;
        v.z = o[i][2] * inv; v.w = o[i][3] * inv;
        uint2 hi, lo;
        split4(v, hi, lo);
        size_t idx = (size_t)(qbase + r0 + i) * DIMC + h * 64 + c0;
        *(uint2*)&g_aoh[idx] = hi;
        *(uint2*)&g_aol[idx] = lo;
    }
}

// ---------------- launch -----------------------------------------------------
extern "C" void kernel_launch(void* const* d_in, const int* in_sizes, int n_in,
                              void* d_out, int out_size) {
    (void)in_sizes; (void)n_in; (void)out_size;
    const float* x     = (const float*)d_in[0];
    const float* ln1_g = (const float*)d_in[1];
    const float* ln1_b = (const float*)d_in[2];
    const float* w_qkv = (const float*)d_in[3];
    const float* w_out = (const float*)d_in[4];
    const float* b_out = (const float*)d_in[5];
    const float* ln2_g = (const float*)d_in[6];
    const float* ln2_b = (const float*)d_in[7];
    const float* w1    = (const float*)d_in[8];
    const float* b1    = (const float*)d_in[9];
    const float* w2    = (const float*)d_in[10];
    const float* b2    = (const float*)d_in[11];
    float* out = (float*)d_out;

    float *qkv, *x2;
    __nv_bfloat16 *h1h, *h1l, *aoh, *aol, *h2h, *h2l, *acth, *actl;
    __nv_bfloat16 *wqkvh, *wqkvl, *wouth, *woutl, *w1h, *w1l, *w2h, *w2l;
    cudaGetSymbolAddress((void**)&qkv,  g_qkv);
    cudaGetSymbolAddress((void**)&x2,   g_x2);
    cudaGetSymbolAddress((void**)&h1h,  g_h1h);  cudaGetSymbolAddress((void**)&h1l,  g_h1l);
    cudaGetSymbolAddress((void**)&aoh,  g_aoh);  cudaGetSymbolAddress((void**)&aol,  g_aol);
    cudaGetSymbolAddress((void**)&h2h,  g_h2h);  cudaGetSymbolAddress((void**)&h2l,  g_h2l);
    cudaGetSymbolAddress((void**)&acth, g_acth); cudaGetSymbolAddress((void**)&actl, g_actl);
    cudaGetSymbolAddress((void**)&wqkvh, g_wqkvh); cudaGetSymbolAddress((void**)&wqkvl, g_wqkvl);
    cudaGetSymbolAddress((void**)&wouth, g_wouth); cudaGetSymbolAddress((void**)&woutl, g_woutl);
    cudaGetSymbolAddress((void**)&w1h, g_w1h); cudaGetSymbolAddress((void**)&w1l, g_w1l);
    cudaGetSymbolAddress((void**)&w2h, g_w2h); cudaGetSymbolAddress((void**)&w2l, g_w2l);

    cudaFuncSetAttribute(attn_kernel,
                         cudaFuncAttributeMaxDynamicSharedMemorySize, 49408);
    cudaFuncSetAttribute(mma_gemm<0>,
                         cudaFuncAttributeMaxDynamicSharedMemorySize, SMEM_TOTAL);
    cudaFuncSetAttribute(mma_gemm<1>,
                         cudaFuncAttributeMaxDynamicSharedMemorySize, SMEM_TOTAL);
    cudaFuncSetAttribute(mma_gemm<2>,
                         cudaFuncAttributeMaxDynamicSharedMemorySize, SMEM_TOTAL);

    // 0) split weights to bf16 hi/lo
    split_kernel<<<(DIMC * QKVD) / 1024, 256>>>(w_qkv, wqkvh, wqkvl);
    split_kernel<<<(DIMC * DIMC) / 1024, 256>>>(w_out, wouth, woutl);
    split_kernel<<<(DIMC * MLPD) / 1024, 256>>>(w1, w1h, w1l);
    split_kernel<<<(MLPD * DIMC) / 1024, 256>>>(w2, w2h, w2l);

    // 1) h1 = LN1(x)   (split bf16)
    ln_kernel<<<TOK, 256>>>(x, ln1_g, ln1_b, h1h, h1l);
    // 2) qkv = h1 @ w_qkv   (fp32 out)
    mma_gemm<0><<<dim3(QKVD / 128, TOK / 128), 256, SMEM_TOTAL>>>(
        h1h, h1l, wqkvh, wqkvl, qkv, (__nv_bfloat16*)0, (__nv_bfloat16*)0,
        TOK, QKVD, DIMC, (const float*)0, (const float*)0);
    // 3) attention -> ao (split bf16)
    attn_kernel<<<dim3(16, 12, 8), 256, 49408>>>();
    // 4) x2 = x + ao @ w_out + b_out   (fp32)
    mma_gemm<1><<<dim3(DIMC / 128, TOK / 128), 256, SMEM_TOTAL>>>(
        aoh, aol, wouth, woutl, x2, (__nv_bfloat16*)0, (__nv_bfloat16*)0,
        TOK, DIMC, DIMC, b_out, x);
    // 5) h2 = LN2(x2)   (split bf16)
    ln_kernel<<<TOK, 256>>>(x2, ln2_g, ln2_b, h2h, h2l);
    // 6) act = gelu(h2 @ w1 + b1)   (split bf16)
    mma_gemm<2><<<dim3(MLPD / 128, TOK / 128), 256, SMEM_TOTAL>>>(
        h2h, h2l, w1h, w1l, (float*)0, acth, actl,
        TOK, MLPD, DIMC, b1, (const float*)0);
    // 7) out = x2 + act @ w2 + b2   (fp32)
    mma_gemm<1><<<dim3(DIMC / 128, TOK / 128), 256, SMEM_TOTAL>>>(
        acth, actl, w2h, w2l, out, (__nv_bfloat16*)0, (__nv_bfloat16*)0,
        TOK, DIMC, MLPD, b2, x2);
}

// round 16
// speedup vs baseline: 1.9833x; 1.0006x over previous
#include <cuda_runtime.h>
#include <cuda_bf16.h>
#include <stdint.h>
#include <cstdint>
#include <math.h>

#define TOK   8192        // 8 * 1024 tokens
#define DIMC  768
#define QKVD  2304
#define MLPD  3072
#define SEQ   1024

#define PADA  40          // A smem row stride (bf16): ldmatrix conflict-free
#define PADB  136         // B smem row stride (bf16): ldmatrix conflict-free
#define A_ELE (128 * PADA)            // 5120 bf16
#define B_ELE (32 * PADB)             // 4352 bf16
#define STAGE_BYTES ((2 * A_ELE + 2 * B_ELE) * 2)   // 37888
#define SMEM_TOTAL  (2 * STAGE_BYTES)               // 75776

// ---------------- scratch (device globals: no allocation allowed) ----------
__device__ float          g_qkv [TOK * QKVD];
__device__ float          g_x2  [TOK * DIMC];
__device__ __nv_bfloat16  g_h1h [TOK * DIMC],  g_h1l [TOK * DIMC];
__device__ __nv_bfloat16  g_aoh [TOK * DIMC],  g_aol [TOK * DIMC];
__device__ __nv_bfloat16  g_h2h [TOK * DIMC],  g_h2l [TOK * DIMC];
__device__ __nv_bfloat16  g_acth[TOK * MLPD],  g_actl[TOK * MLPD];
__device__ __nv_bfloat16  g_wqkvh[DIMC * QKVD], g_wqkvl[DIMC * QKVD];
__device__ __nv_bfloat16  g_wouth[DIMC * DIMC], g_woutl[DIMC * DIMC];
__device__ __nv_bfloat16  g_w1h  [DIMC * MLPD], g_w1l  [DIMC * MLPD];
__device__ __nv_bfloat16  g_w2h  [MLPD * DIMC], g_w2l  [MLPD * DIMC];

// ---------------- helpers ----------------------------------------------------
__device__ __forceinline__ unsigned int packbf(float a, float b) {
    __nv_bfloat162 t = __floats2bfloat162_rn(a, b);
    return *(unsigned int*)&t;
}
__device__ __forceinline__ void split4(float4 v, uint2& hi, uint2& lo) {
    float hx = __bfloat162float(__float2bfloat16(v.x));
    float hy = __bfloat162float(__float2bfloat16(v.y));
    float hz = __bfloat162float(__float2bfloat16(v.z));
    float hw = __bfloat162float(__float2bfloat16(v.w));
    hi.x = packbf(hx, hy);
    hi.y = packbf(hz, hw);
    lo.x = packbf(v.x - hx, v.y - hy);
    lo.y = packbf(v.z - hz, v.w - hw);
}
__device__ __forceinline__ void ldsm_x4(unsigned int* r, unsigned int addr) {
    asm volatile("ldmatrix.sync.aligned.m8n8.x4.shared.b16 {%0,%1,%2,%3}, [%4];"
                 : "=r"(r[0]), "=r"(r[1]), "=r"(r[2]), "=r"(r[3]) : "r"(addr));
}
__device__ __forceinline__ void ldsm_x2t(unsigned int* r, unsigned int addr) {
    asm volatile("ldmatrix.sync.aligned.m8n8.x2.trans.shared.b16 {%0,%1}, [%2];"
                 : "=r"(r[0]), "=r"(r[1]) : "r"(addr));
}
__device__ __forceinline__ void mma_bf16(float* d, const unsigned int* a,
                                         const unsigned int* b) {
    asm volatile(
        "mma.sync.aligned.m16n8k16.row.col.f32.bf16.bf16.f32 "
        "{%0,%1,%2,%3}, {%4,%5,%6,%7}, {%8,%9}, {%0,%1,%2,%3};"
        : "+f"(d[0]), "+f"(d[1]), "+f"(d[2]), "+f"(d[3])
        : "r"(a[0]), "r"(a[1]), "r"(a[2]), "r"(a[3]), "r"(b[0]), "r"(b[1]));
}
__device__ __forceinline__ void cpa16(unsigned int dst, const void* src) {
    asm volatile("cp.async.cg.shared.global [%0], [%1], 16;" :: "r"(dst), "l"(src));
}

// ---------------- weight split: fp32 -> bf16 hi/lo ---------------------------
__global__ void __launch_bounds__(256) split_kernel(const float* __restrict__ w,
                                                    __nv_bfloat16* __restrict__ hi,
                                                    __nv_bfloat16* __restrict__ lo) {
    int i = (blockIdx.x * 256 + threadIdx.x) * 4;
    float4 v = *(const float4*)(w + i);
    uint2 h, l;
    split4(v, h, l);
    *(uint2*)&hi[i] = h;
    *(uint2*)&lo[i] = l;
}

// ---------------- LayerNorm -> bf16 hi/lo ------------------------------------
__global__ void __launch_bounds__(256) ln_kernel(const float* __restrict__ x,
                                                 const float* __restrict__ g,
                                                 const float* __restrict__ b,
                                                 __nv_bfloat16* __restrict__ oh,
                                                 __nv_bfloat16* __restrict__ ol) {
    int row = blockIdx.x;
    int t = threadIdx.x;
    const float* xr = x + (size_t)row * DIMC;
    float v0 = xr[t], v1 = xr[t + 256], v2 = xr[t + 512];
    float s  = v0 + v1 + v2;
    float s2 = v0 * v0 + v1 * v1 + v2 * v2;
#pragma unroll
    for (int off = 16; off; off >>= 1) {
        s  += __shfl_xor_sync(0xffffffffu, s,  off);
        s2 += __shfl_xor_sync(0xffffffffu, s2, off);
    }
    __shared__ float rs[8], rs2[8];
    int w = t >> 5;
    if ((t & 31) == 0) { rs[w] = s; rs2[w] = s2; }
    __syncthreads();
    s = 0.f; s2 = 0.f;
#pragma unroll
    for (int i = 0; i < 8; i++) { s += rs[i]; s2 += rs2[i]; }
    float mu   = s  * (1.0f / DIMC);
    float var  = s2 * (1.0f / DIMC) - mu * mu;
    float rstd = rsqrtf(var + 1e-5f);
#pragma unroll
    for (int j = 0; j < 3; j++) {
        int c = t + (j << 8);
        float v = (j == 0) ? v0 : (j == 1) ? v1 : v2;
        float y = (v - mu) * rstd * g[c] + b[c];
        __nv_bfloat16 hb = __float2bfloat16(y);
        oh[(size_t)row * DIMC + c] = hb;
        ol[(size_t)row * DIMC + c] = __float2bfloat16(y - __bfloat162float(hb));
    }
}

// ---------------- split-bf16 tensor-core GEMM, cp.async double-buffered ------
// C(MxN) = A(MxK) @ B(KxN); A,B given pre-split as bf16 hi/lo pairs.
// acc = Ah*Bh + Ah*Bl + Al*Bh (fp32).  CTA tile 128x128, K-tile 32, 8 warps.
// EPI 0: C fp32 = AB
// EPI 1: C fp32 = AB + bias[n] + res[m][n]
// EPI 2: Ch/Cl bf16 split = gelu_exact(AB + bias[n])
template <int EPI>
__global__ void __launch_bounds__(256, 2) mma_gemm(
    const __nv_bfloat16* __restrict__ Agh, const __nv_bfloat16* __restrict__ Agl,
    const __nv_bfloat16* __restrict__ Bgh, const __nv_bfloat16* __restrict__ Bgl,
    float* __restrict__ C, __nv_bfloat16* __restrict__ Ch, __nv_bfloat16* __restrict__ Cl,
    int M, int N, int K,
    const float* __restrict__ bias, const float* __restrict__ res) {
    extern __shared__ __nv_bfloat16 sm_bf[];
    unsigned int smem_u = (unsigned int)__cvta_generic_to_shared(sm_bf);

    int t = threadIdx.x;
    int lane = t & 31, wid = t >> 5;
    int wm = (wid >> 2) << 6;
    int wn = (wid & 3) << 5;
    int bm = blockIdx.y << 7, bn = blockIdx.x << 7;

    const __nv_bfloat16* Ah_g = Agh + (size_t)bm * K;
    const __nv_bfloat16* Al_g = Agl + (size_t)bm * K;
    const __nv_bfloat16* Bh_g = Bgh + bn;
    const __nv_bfloat16* Bl_g = Bgl + bn;

    float acc[4][4][4];
#pragma unroll
    for (int mi = 0; mi < 4; mi++)
#pragma unroll
        for (int ni = 0; ni < 4; ni++)
#pragma unroll
            for (int k = 0; k < 4; k++) acc[mi][ni][k] = 0.f;

    // per-lane fragment offsets (bytes, within a stage)
    unsigned int aoff = (unsigned int)(((wm + (lane & 15)) * PADA + ((lane >> 4) << 3)) * 2);
    unsigned int boff = (unsigned int)(((lane & 15) * PADB + wn) * 2);

    // per-thread cp.async chunk coordinates
    int ar0 = t >> 2,  ac0 = (t & 3) << 3;            // A: chunks t, t+256
    int ar1 = (t + 256) >> 2, ac1 = ((t + 256) & 3) << 3;
    int br0 = t >> 4,  bc0 = (t & 15) << 3;           // B: chunks t, t+256
    int br1 = (t + 256) >> 4, bc1 = ((t + 256) & 15) << 3;

#define LOAD_STAGE(SB, K0)                                                         \
    do {                                                                           \
        unsigned int aH = (SB), aL = (SB) + A_ELE * 2;                             \
        unsigned int bH = (SB) + 4 * A_ELE, bL = bH + B_ELE * 2;                   \
        cpa16(aH + (unsigned int)(ar0 * PADA + ac0) * 2, Ah_g + (size_t)ar0 * K + (K0) + ac0); \
        cpa16(aH + (unsigned int)(ar1 * PADA + ac1) * 2, Ah_g + (size_t)ar1 * K + (K0) + ac1); \
        cpa16(aL + (unsigned int)(ar0 * PADA + ac0) * 2, Al_g + (size_t)ar0 * K + (K0) + ac0); \
        cpa16(aL + (unsigned int)(ar1 * PADA + ac1) * 2, Al_g + (size_t)ar1 * K + (K0) + ac1); \
        cpa16(bH + (unsigned int)(br0 * PADB + bc0) * 2, Bh_g + (size_t)((K0) + br0) * N + bc0); \
        cpa16(bH + (unsigned int)(br1 * PADB + bc1) * 2, Bh_g + (size_t)((K0) + br1) * N + bc1); \
        cpa16(bL + (unsigned int)(br0 * PADB + bc0) * 2, Bl_g + (size_t)((K0) + br0) * N + bc0); \
        cpa16(bL + (unsigned int)(br1 * PADB + bc1) * 2, Bl_g + (size_t)((K0) + br1) * N + bc1); \
        asm volatile("cp.async.commit_group;");                                    \
    } while (0)

    int nk = K >> 5;
    LOAD_STAGE(smem_u, 0);

    for (int kt = 0; kt < nk; kt++) {
        unsigned int cur = smem_u + (unsigned int)(kt & 1) * STAGE_BYTES;
        if (kt + 1 < nk) {
            unsigned int nxt = smem_u + (unsigned int)((kt + 1) & 1) * STAGE_BYTES;
            LOAD_STAGE(nxt, (kt + 1) << 5);
            asm volatile("cp.async.wait_group 1;");
        } else {
            asm volatile("cp.async.wait_group 0;");
        }
        __syncthreads();

        unsigned int baseAh = cur + aoff;
        unsigned int baseAl = baseAh + A_ELE * 2;
        unsigned int baseBh = cur + 4 * A_ELE + boff;
        unsigned int baseBl = baseBh + B_ELE * 2;

#pragma unroll
        for (int ks = 0; ks < 32; ks += 16) {
            unsigned int ah[4][4], al[4][4], bf[4][2];
#pragma unroll
            for (int mi = 0; mi < 4; mi++)
                ldsm_x4(ah[mi], baseAh + (unsigned int)(ks * 2 + mi * 16 * PADA * 2));
#pragma unroll
            for (int mi = 0; mi < 4; mi++)
                ldsm_x4(al[mi], baseAl + (unsigned int)(ks * 2 + mi * 16 * PADA * 2));
            // B hi: used by Ah and Al passes
#pragma unroll
            for (int ni = 0; ni < 4; ni++)
                ldsm_x2t(bf[ni], baseBh + (unsigned int)(ks * PADB * 2 + ni * 16));
#pragma unroll
            for (int mi = 0; mi < 4; mi++)
#pragma unroll
                for (int ni = 0; ni < 4; ni++)
                    mma_bf16(acc[mi][ni], ah[mi], bf[ni]);
#pragma unroll
            for (int mi = 0; mi < 4; mi++)
#pragma unroll
                for (int ni = 0; ni < 4; ni++)
                    mma_bf16(acc[mi][ni], al[mi], bf[ni]);
            // B lo: only Ah pass
#pragma unroll
            for (int ni = 0; ni < 4; ni++)
                ldsm_x2t(bf[ni], baseBl + (unsigned int)(ks * PADB * 2 + ni * 16));
#pragma unroll
            for (int mi = 0; mi < 4; mi++)
#pragma unroll
                for (int ni = 0; ni < 4; ni++)
                    mma_bf16(acc[mi][ni], ah[mi], bf[ni]);
        }
        __syncthreads();
    }

    // epilogue
#pragma unroll
    for (int mi = 0; mi < 4; mi++) {
        int rbase = bm + wm + mi * 16 + (lane >> 2);
#pragma unroll
        for (int ni = 0; ni < 4; ni++) {
            int c = bn + wn + ni * 8 + ((lane & 3) << 1);
#pragma unroll
            for (int hh = 0; hh < 2; hh++) {
                int r = rbase + (hh << 3);
                float2 v = make_float2(acc[mi][ni][hh * 2], acc[mi][ni][hh * 2 + 1]);
                if (EPI == 0) {
                    *(float2*)&C[(size_t)r * N + c] = v;
                }
                if (EPI == 1) {
                    float2 bs = *(const float2*)&bias[c];
                    float2 rr = *(const float2*)&res[(size_t)r * N + c];
                    v.x += bs.x + rr.x;
                    v.y += bs.y + rr.y;
                    *(float2*)&C[(size_t)r * N + c] = v;
                }
                if (EPI == 2) {
                    float2 bs = *(const float2*)&bias[c];
                    v.x += bs.x;
                    v.y += bs.y;
                    const float rs2i = 0.70710678118654752f;
                    v.x = 0.5f * v.x * (1.0f + erff(v.x * rs2i));
                    v.y = 0.5f * v.y * (1.0f + erff(v.y * rs2i));
                    float hx = __bfloat162float(__float2bfloat16(v.x));
                    float hy = __bfloat162float(__float2bfloat16(v.y));
                    *(unsigned int*)&Ch[(size_t)r * N + c] = packbf(hx, hy);
                    *(unsigned int*)&Cl[(size_t)r * N + c] = packbf(v.x - hx, v.y - hy);
                }
            }
        }
    }
}

// ---------------- fused flash attention (fp32, writes split bf16) ------------
__global__ void __launch_bounds__(256) attn_kernel() {
    extern __shared__ float sm[];
    float* Qs  = sm;          // [64][64]
    float* KPs = sm + 4096;   // [64][65]
    float* Vs  = sm + 8256;   // [64][64]

    int t  = threadIdx.x;
    int tx = t & 15, ty = t >> 4;
    int r0 = ty << 2, c0 = tx << 2;
    int qb = blockIdx.x, h = blockIdx.y, b = blockIdx.z;
    int qbase = b * SEQ + qb * 64;
    const float scale = 0.125f;

    for (int i = t; i < 1024; i += 256) {
        int row = i >> 4, d4 = (i & 15) << 2;
        float4 q4 = *(const float4*)&g_qkv[(size_t)(qbase + row) * QKVD + h * 64 + d4];
        *(float4*)&Qs[row * 64 + d4] = q4;
    }

    float o[4][4];
    float m[4], l[4];
#pragma unroll
    for (int i = 0; i < 4; i++) {
        m[i] = -1e30f; l[i] = 0.f;
#pragma unroll
        for (int j = 0; j < 4; j++) o[i][j] = 0.f;
    }

    for (int kb = 0; kb < 16; kb++) {
        int kvb = b * SEQ + kb * 64;
        __syncthreads();
        for (int i = t; i < 1024; i += 256) {
            int row = i >> 4, d4 = (i & 15) << 2;
            float4 k4 = *(const float4*)&g_qkv[(size_t)(kvb + row) * QKVD + 768 + h * 64 + d4];
            float* kp = &KPs[row * 65 + d4];
            kp[0] = k4.x; kp[1] = k4.y; kp[2] = k4.z; kp[3] = k4.w;
            float4 v4 = *(const float4*)&g_qkv[(size_t)(kvb + row) * QKVD + 1536 + h * 64 + d4];
            *(float4*)&Vs[row * 64 + d4] = v4;
        }
        __syncthreads();

        float s[4][4];
#pragma unroll
        for (int i = 0; i < 4; i++)
#pragma unroll
            for (int j = 0; j < 4; j++) s[i][j] = 0.f;
        for (int d = 0; d < 64; d++) {
            float qf[4], kf[4];
#pragma unroll
            for (int i = 0; i < 4; i++) qf[i] = Qs[(r0 + i) * 64 + d];
#pragma unroll
            for (int j = 0; j < 4; j++) kf[j] = KPs[(c0 + j) * 65 + d];
#pragma unroll
            for (int i = 0; i < 4; i++)
#pragma unroll
                for (int j = 0; j < 4; j++)
                    s[i][j] = fmaf(qf[i], kf[j], s[i][j]);
        }

#pragma unroll
        for (int i = 0; i < 4; i++) {
#pragma unroll
            for (int j = 0; j < 4; j++) s[i][j] *= scale;
            float mx = fmaxf(fmaxf(s[i][0], s[i][1]), fmaxf(s[i][2], s[i][3]));
#pragma unroll
            for (int off = 8; off; off >>= 1)
                mx = fmaxf(mx, __shfl_xor_sync(0xffffffffu, mx, off));
            float mn = fmaxf(m[i], mx);
            float f  = __expf(m[i] - mn);
            m[i] = mn;
            float sum = 0.f;
#pragma unroll
            for (int j = 0; j < 4; j++) {
                s[i][j] = __expf(s[i][j] - mn);
                sum += s[i][j];
            }
#pragma unroll
            for (int off = 8; off; off >>= 1)
                sum += __shfl_xor_sync(0xffffffffu, sum, off);
            l[i] = l[i] * f + sum;
#pragma unroll
            for (int j = 0; j < 4; j++) o[i][j] *= f;
        }

        __syncthreads();
#pragma unroll
        for (int i = 0; i < 4; i++)
#pragma unroll
            for (int j = 0; j < 4; j++)
                KPs[(r0 + i) * 65 + c0 + j] = s[i][j];
        __syncthreads();

        for (int j = 0; j < 64; j++) {
            float pf[4];
#pragma unroll
            for (int i = 0; i < 4; i++) pf[i] = KPs[(r0 + i) * 65 + j];
            float4 v4 = *(const float4*)&Vs[j * 64 + c0];
#pragma unroll
            for (int i = 0; i < 4; i++) {
                o[i][0] = fmaf(pf[i], v4.x, o[i][0]);
                o[i][1] = fmaf(pf[i], v4.y, o[i][1]);
                o[i][2] = fmaf(pf[i], v4.z, o[i][2]);
                o[i][3] = fmaf(pf[i], v4.w, o[i][3]);
            }
        }
    }

#pragma unroll
    for (int i = 0; i < 4; i++) {
        float inv = 1.0f / l[i];
        float4 v;
        v.x = o[i][0] * inv; v.y = o[i][1] * inv;
        v.z = o[i][2] * inv; v.w = o[i][3] * inv;
        uint2 hi, lo;
        split4(v, hi, lo);
        size_t idx = (size_t)(qbase + r0 + i) * DIMC + h * 64 + c0;
        *(uint2*)&g_aoh[idx] = hi;
        *(uint2*)&g_aol[idx] = lo;
    }
}

// ---------------- launch -----------------------------------------------------
extern "C" void kernel_launch(void* const* d_in, const int* in_sizes, int n_in,
                              void* d_out, int out_size) {
    (void)in_sizes; (void)n_in; (void)out_size;
    const float* x     = (const float*)d_in[0];
    const float* ln1_g = (const float*)d_in[1];
    const float* ln1_b = (const float*)d_in[2];
    const float* w_qkv = (const float*)d_in[3];
    const float* w_out = (const float*)d_in[4];
    const float* b_out = (const float*)d_in[5];
    const float* ln2_g = (const float*)d_in[6];
    const float* ln2_b = (const float*)d_in[7];
    const float* w1    = (const float*)d_in[8];
    const float* b1    = (const float*)d_in[9];
    const float* w2    = (const float*)d_in[10];
    const float* b2    = (const float*)d_in[11];
    float* out = (float*)d_out;

    float *qkv, *x2;
    __nv_bfloat16 *h1h, *h1l, *aoh, *aol, *h2h, *h2l, *acth, *actl;
    __nv_bfloat16 *wqkvh, *wqkvl, *wouth, *woutl, *w1h, *w1l, *w2h, *w2l;
    cudaGetSymbolAddress((void**)&qkv,  g_qkv);
    cudaGetSymbolAddress((void**)&x2,   g_x2);
    cudaGetSymbolAddress((void**)&h1h,  g_h1h);  cudaGetSymbolAddress((void**)&h1l,  g_h1l);
    cudaGetSymbolAddress((void**)&aoh,  g_aoh);  cudaGetSymbolAddress((void**)&aol,  g_aol);
    cudaGetSymbolAddress((void**)&h2h,  g_h2h);  cudaGetSymbolAddress((void**)&h2l,  g_h2l);
    cudaGetSymbolAddress((void**)&acth, g_acth); cudaGetSymbolAddress((void**)&actl, g_actl);
    cudaGetSymbolAddress((void**)&wqkvh, g_wqkvh); cudaGetSymbolAddress((void**)&wqkvl, g_wqkvl);
    cudaGetSymbolAddress((void**)&wouth, g_wouth); cudaGetSymbolAddress((void**)&woutl, g_woutl);
    cudaGetSymbolAddress((void**)&w1h, g_w1h); cudaGetSymbolAddress((void**)&w1l, g_w1l);
    cudaGetSymbolAddress((void**)&w2h, g_w2h); cudaGetSymbolAddress((void**)&w2l, g_w2l);

    cudaFuncSetAttribute(attn_kernel,
                         cudaFuncAttributeMaxDynamicSharedMemorySize, 49408);
    cudaFuncSetAttribute(mma_gemm<0>,
                         cudaFuncAttributeMaxDynamicSharedMemorySize, SMEM_TOTAL);
    cudaFuncSetAttribute(mma_gemm<1>,
                         cudaFuncAttributeMaxDynamicSharedMemorySize, SMEM_TOTAL);
    cudaFuncSetAttribute(mma_gemm<2>,
                         cudaFuncAttributeMaxDynamicSharedMemorySize, SMEM_TOTAL);

    // 0) split weights to bf16 hi/lo
    split_kernel<<<(DIMC * QKVD) / 1024, 256>>>(w_qkv, wqkvh, wqkvl);
    split_kernel<<<(DIMC * DIMC) / 1024, 256>>>(w_out, wouth, woutl);
    split_kernel<<<(DIMC * MLPD) / 1024, 256>>>(w1, w1h, w1l);
    split_kernel<<<(MLPD * DIMC) / 1024, 256>>>(w2, w2h, w2l);

    // 1) h1 = LN1(x)   (split bf16)
    ln_kernel<<<TOK, 256>>>(x, ln1_g, ln1_b, h1h, h1l);
    // 2) qkv = h1 @ w_qkv   (fp32 out)
    mma_gemm<0><<<dim3(QKVD / 128, TOK / 128), 256, SMEM_TOTAL>>>(
        h1h, h1l, wqkvh, wqkvl, qkv, (__nv_bfloat16*)0, (__nv_bfloat16*)0,
        TOK, QKVD, DIMC, (const float*)0, (const float*)0);
    // 3) attention -> ao (split bf16)
    attn_kernel<<<dim3(16, 12, 8), 256, 49408>>>();
    // 4) x2 = x + ao @ w_out + b_out   (fp32)
    mma_gemm<1><<<dim3(DIMC / 128, TOK / 128), 256, SMEM_TOTAL>>>(
        aoh, aol, wouth, woutl, x2, (__nv_bfloat16*)0, (__nv_bfloat16*)0,
        TOK, DIMC, DIMC, b_out, x);
    // 5) h2 = LN2(x2)   (split bf16)
    ln_kernel<<<TOK, 256>>>(x2, ln2_g, ln2_b, h2h, h2l);
    // 6) act = gelu(h2 @ w1 + b1)   (split bf16)
    mma_gemm<2><<<dim3(MLPD / 128, TOK / 128), 256, SMEM_TOTAL>>>(
        h2h, h2l, w1h, w1l, (float*)0, acth, actl,
        TOK, MLPD, DIMC, b1, (const float*)0);
    // 7) out = x2 + act @ w2 + b2   (fp32)
    mma_gemm<1><<<dim3(DIMC / 128, TOK / 128), 256, SMEM_TOTAL>>>(
        acth, actl, w2h, w2l, out, (__nv_bfloat16*)0, (__nv_bfloat16*)0,
        TOK, DIMC, MLPD, b2, x2);
}